// round 12
// baseline (speedup 1.0000x reference)
#include <cuda_runtime.h>
#include <cuda_fp16.h>
#include <cstdint>
#include <cstddef>

#define DEVINL __device__ __forceinline__
using u32 = uint32_t;
using ull = unsigned long long;

constexpr int D  = 512;
constexpr int NC = 128;

constexpr int TILE_B   = 16384;            // one 128-row x 128B packed tile (hi|lo)
constexpr int STAGE_B  = 2 * TILE_B;       // A tile + B tile
constexpr int NSTAGE   = 3;
constexpr int LOOP_SMEM = NSTAGE * STAGE_B;            // 98304
constexpr int FUSED_SMEM = LOOP_SMEM + 512 + 4096 + 512;  // + tvec + wb + bidx

__device__ float g_tvec[NC];               // ||c||^2 - 2 b.c
__device__ float g_efp32[NC * D];          // E = CB @ W (fp32)
__device__ __align__(128) char g_xsplit[256][16][TILE_B];   // 64 MB
__device__ __align__(128) char g_wsplit[4][16][TILE_B];     // 1 MB
__device__ __align__(128) char g_esplit[16][TILE_B];        // 256 KB

// ---------------------------------------------------------------- helpers
DEVINL u32 smem_u32(const void* p) {
    u32 a;
    asm("{ .reg .u64 t; cvta.to.shared.u64 t, %1; cvt.u32.u64 %0, t; }"
        : "=r"(a) : "l"(p));
    return a;
}
DEVINL void ldsm4(u32& r0, u32& r1, u32& r2, u32& r3, u32 a) {
    asm volatile("ldmatrix.sync.aligned.m8n8.x4.shared.b16 {%0,%1,%2,%3}, [%4];"
                 : "=r"(r0), "=r"(r1), "=r"(r2), "=r"(r3) : "r"(a));
}
DEVINL void mma_f16(float c[4], const u32 a[4], const u32 b[2]) {
    asm volatile(
        "mma.sync.aligned.m16n8k16.row.col.f32.f16.f16.f32 "
        "{%0,%1,%2,%3},{%4,%5,%6,%7},{%8,%9},{%0,%1,%2,%3};"
        : "+f"(c[0]), "+f"(c[1]), "+f"(c[2]), "+f"(c[3])
        : "r"(a[0]), "r"(a[1]), "r"(a[2]), "r"(a[3]), "r"(b[0]), "r"(b[1]));
}
DEVINL u32 pack_h2(__half a, __half b) {
    __half2 h = __halves2half2(a, b);
    return *reinterpret_cast<u32*>(&h);
}
DEVINL void fsplit(float x, __half& h, __half& l) {
    h = __float2half_rn(x);
    l = __float2half_rn(x - __half2float(h));
}
DEVINL void cp16(u32 dst, const void* src) {
    asm volatile("cp.async.cg.shared.global [%0], [%1], 16;" :: "r"(dst), "l"(src));
}
DEVINL void cp_commit() { asm volatile("cp.async.commit_group;" ::: "memory"); }
DEVINL void cp_wait1()  { asm volatile("cp.async.wait_group 1;" ::: "memory"); }
DEVINL void cp_wait0()  { asm volatile("cp.async.wait_group 0;" ::: "memory"); }

// split 16 fp32 into 2 hi + 2 lo 16B chunks of a packed tile row.
// hi chunk c at ((c^e)<<4), lo at (((c^4)^e)<<4), e = row&7.
DEVINL void split16(const float4 v[4], char* drow, int c0, int e) {
    #pragma unroll
    for (int c2 = 0; c2 < 2; ++c2) {
        const float f[8] = { v[2*c2].x, v[2*c2].y, v[2*c2].z, v[2*c2].w,
                             v[2*c2+1].x, v[2*c2+1].y, v[2*c2+1].z, v[2*c2+1].w };
        __half hh[8], ll[8];
        #pragma unroll
        for (int j = 0; j < 8; ++j) fsplit(f[j], hh[j], ll[j]);
        uint4 uh = make_uint4(pack_h2(hh[0], hh[1]), pack_h2(hh[2], hh[3]),
                              pack_h2(hh[4], hh[5]), pack_h2(hh[6], hh[7]));
        uint4 ul = make_uint4(pack_h2(ll[0], ll[1]), pack_h2(ll[2], ll[3]),
                              pack_h2(ll[4], ll[5]), pack_h2(ll[6], ll[7]));
        const int c = c0 + c2;
        *(uint4*)(drow + (((c)     ^ e) << 4)) = uh;
        *(uint4*)(drow + (((c ^ 4) ^ e) << 4)) = ul;
    }
}

// ---------------------------------------------------------------- prepass 1
// b<64: E compute (4 cb rows per W read). [64,128): W tiles. [128,128+2048): X (2 slices/block).
__global__ void prepass1_kernel(const float* __restrict__ X,
                                const float* __restrict__ W,
                                const float* __restrict__ CB) {
    __shared__ __align__(16) char st[2 * TILE_B];
    const int b = blockIdx.x;
    const int tid = threadIdx.x;

    if (b < 64) {
        // group g = b>>1 covers codebook rows 4g..4g+3; col = (b&1)*256 + tid
        const int g = b >> 1;
        const int c = (b & 1) * 256 + tid;
        const float* wc  = W + c;
        const float* cb0 = CB + (size_t)(g * 4) * D;
        float a0 = 0.f, a1 = 0.f, a2 = 0.f, a3 = 0.f;
        #pragma unroll 4
        for (int k = 0; k < D; ++k) {
            const float wv = wc[(size_t)k * D];
            a0 = fmaf(cb0[k],         wv, a0);
            a1 = fmaf(cb0[k + D],     wv, a1);
            a2 = fmaf(cb0[k + 2 * D], wv, a2);
            a3 = fmaf(cb0[k + 3 * D], wv, a3);
        }
        g_efp32[(size_t)(g * 4 + 0) * D + c] = a0;
        g_efp32[(size_t)(g * 4 + 1) * D + c] = a1;
        g_efp32[(size_t)(g * 4 + 2) * D + c] = a2;
        g_efp32[(size_t)(g * 4 + 3) * D + c] = a3;
        return;
    }

    const int r = tid >> 1, h = tid & 1, e = r & 7;
    if (b < 128) {
        // W tile, single slice
        const int bb = b - 64;
        const int ct = bb >> 4, s = bb & 15;
        const float* src0 = W + (size_t)(ct * 128 + r) * D + s * 32 + h * 16;
        float4 v[4];
        #pragma unroll
        for (int i = 0; i < 4; ++i) v[i] = ((const float4*)src0)[i];
        split16(v, &st[r * 128], h * 2, e);
        __syncthreads();
        char* dst = &g_wsplit[ct][s][0];
        #pragma unroll
        for (int k = 0; k < 4; ++k)
            *(uint4*)(dst + tid * 16 + k * 4096) = *(const uint4*)(st + tid * 16 + k * 4096);
        return;
    }

    // X tiles: 2 slices per block for doubled MLP
    const int bb = b - 128;
    const int rb = bb >> 3, s0 = (bb & 7) * 2;
    const float4* p0 = (const float4*)(X + (size_t)(rb * 128 + r) * D + s0 * 32 + h * 16);
    const float4* p1 = (const float4*)(X + (size_t)(rb * 128 + r) * D + (s0 + 1) * 32 + h * 16);
    float4 v0[4], v1[4];
    #pragma unroll
    for (int i = 0; i < 4; ++i) v0[i] = p0[i];
    #pragma unroll
    for (int i = 0; i < 4; ++i) v1[i] = p1[i];
    split16(v0, &st[r * 128], h * 2, e);
    split16(v1, &st[TILE_B + r * 128], h * 2, e);
    __syncthreads();
    char* dst0 = &g_xsplit[rb][s0][0];
    #pragma unroll
    for (int k = 0; k < 8; ++k)
        *(uint4*)(dst0 + tid * 16 + k * 4096) = *(const uint4*)(st + tid * 16 + k * 4096);
}

// ---------------------------------------------------------------- prepass 2 (after E): E split + tvec
__global__ void prepass2_kernel(const float* __restrict__ B,
                                const float* __restrict__ CB) {
    __shared__ __align__(16) char st[TILE_B];
    const int b = blockIdx.x;
    const int tid = threadIdx.x, r = tid >> 1, h = tid & 1;

    if (b < 16) {
        const float* src0 = g_efp32 + (size_t)r * D + b * 32 + h * 16;
        float4 v[4];
        #pragma unroll
        for (int i = 0; i < 4; ++i) v[i] = ((const float4*)src0)[i];
        split16(v, &st[r * 128], h * 2, r & 7);
        __syncthreads();
        char* dst = &g_esplit[b][0];
        #pragma unroll
        for (int k = 0; k < 4; ++k)
            *(uint4*)(dst + tid * 16 + k * 4096) = *(const uint4*)(st + tid * 16 + k * 4096);
        return;
    }
    // tvec
    const int c = tid >> 1;
    const float* cp = CB + (size_t)c * D + h * 256;
    const float* bp = B + h * 256;
    float s2 = 0.f, sb = 0.f;
    #pragma unroll 4
    for (int k = 0; k < 64; ++k) {
        float4 v = ((const float4*)cp)[k];
        float4 bv = ((const float4*)bp)[k];
        s2 += v.x * v.x + v.y * v.y + v.z * v.z + v.w * v.w;
        sb += v.x * bv.x + v.y * bv.y + v.z * bv.z + v.w * bv.w;
    }
    s2 += __shfl_xor_sync(0xffffffffu, s2, 1);
    sb += __shfl_xor_sync(0xffffffffu, sb, 1);
    if (!h) g_tvec[c] = s2 - 2.f * sb;
}

// ---------------------------------------------------------------- per-stage MMA (128x128x32, split-2)
DEVINL void stage_mma(u32 aT, int tid, float acc[4][4][4]) {
    const int lane = tid & 31, w = tid >> 5;
    const int mw = w >> 2, nw = w & 3;
    const int eL = lane & 7;
    const int rA = lane & 15, cAk = lane >> 4;
    const int rB0 = nw * 32 + ((lane >> 4) << 3) + (lane & 7);
    const int cBk = (lane >> 3) & 1;
    const u32 bT = aT + TILE_B;

    #pragma unroll
    for (int kk = 0; kk < 2; ++kk) {
        u32 ahi[4][4], alo[4][4], bhi[4][2], blo[4][2];
        const int swA = (kk * 2 + cAk) ^ eL;
        #pragma unroll
        for (int mb = 0; mb < 4; ++mb) {
            const u32 base = aT + (mw * 64 + mb * 16 + rA) * 128;
            ldsm4(ahi[mb][0], ahi[mb][1], ahi[mb][2], ahi[mb][3], base + (swA << 4));
            ldsm4(alo[mb][0], alo[mb][1], alo[mb][2], alo[mb][3], base + ((swA ^ 4) << 4));
        }
        const int swB = (kk * 2 + cBk) ^ eL;
        #pragma unroll
        for (int bp = 0; bp < 2; ++bp) {
            const u32 base = bT + (rB0 + bp * 16) * 128;
            u32 r0, r1, r2, r3;
            ldsm4(r0, r1, r2, r3, base + (swB << 4));
            bhi[bp*2][0] = r0; bhi[bp*2][1] = r1;
            bhi[bp*2+1][0] = r2; bhi[bp*2+1][1] = r3;
            ldsm4(r0, r1, r2, r3, base + ((swB ^ 4) << 4));
            blo[bp*2][0] = r0; blo[bp*2][1] = r1;
            blo[bp*2+1][0] = r2; blo[bp*2+1][1] = r3;
        }
        #pragma unroll
        for (int mb = 0; mb < 4; ++mb)
            #pragma unroll
            for (int nb = 0; nb < 4; ++nb) {
                mma_f16(acc[mb][nb], ahi[mb], bhi[nb]);
                mma_f16(acc[mb][nb], ahi[mb], blo[nb]);
                mma_f16(acc[mb][nb], alo[mb], bhi[nb]);
            }
    }
}

// ---------------------------------------------------------------- fused GEMM + VQ
// grid (5, 256): ct<4 -> Z tile epilogue; ct==4 -> B=E, argmin + gather epilogue.
__global__ void __launch_bounds__(256, 2)
fused_hmma(const float* __restrict__ bias, const float* __restrict__ CB,
           float* __restrict__ Z, float* __restrict__ Q1, float* __restrict__ Q2)
{
    extern __shared__ char smc[];
    float* scn  = (float*)(smc + LOOP_SMEM);
    ull*   wb   = (ull*)  (smc + LOOP_SMEM + 512);
    int*   bidx = (int*)  (smc + LOOP_SMEM + 512 + 4096);

    const u32 sb = smem_u32(smc);
    const int tid = threadIdx.x;
    const int ct = blockIdx.x, rb = blockIdx.y;      // ct fast -> X L2 reuse
    const int li = tid & 127;

    if (ct == 4 && tid < NC) scn[tid] = g_tvec[tid];

    const char* srcBase = (tid < 128) ? &g_xsplit[rb][0][0]
                        : (ct < 4 ? &g_wsplit[ct][0][0] : &g_esplit[0][0]);
    const u32 dstBase = ((tid < 128) ? 0u : (u32)TILE_B) + li * 16;

    #define F_ISSUE(s, buf) do {                                              \
        const char* _src = srcBase + (s) * TILE_B + li * 16;                  \
        const u32 _d = sb + (buf) * STAGE_B + dstBase;                        \
        _Pragma("unroll")                                                     \
        for (int _k = 0; _k < 8; ++_k) cp16(_d + _k * 2048, _src + _k * 2048);\
    } while (0)

    F_ISSUE(0, 0); cp_commit();
    F_ISSUE(1, 1); cp_commit();

    float acc[4][4][4] = {};
    int buf = 0;
    #pragma unroll 1
    for (int s = 0; s < 16; ++s) {
        cp_wait1();
        __syncthreads();
        int b2 = buf + 2; if (b2 >= 3) b2 -= 3;
        if (s + 2 < 16) F_ISSUE(s + 2, b2);
        cp_commit();
        stage_mma(sb + buf * STAGE_B, tid, acc);
        if (++buf == 3) buf = 0;
    }
    #undef F_ISSUE

    cp_wait0();
    __syncthreads();

    const int lane = tid & 31, w = tid >> 5;
    const int mw = w >> 2, nw = w & 3;
    const int row0 = rb * 128;

    if (ct < 4) {
        // ---- Z epilogue: stage in smem, add bias, coalesced fp32 store
        float* zs = (float*)smc;                      // [128][132] = 67584 B
        const int col0 = ct * 128;
        #pragma unroll
        for (int nb = 0; nb < 4; ++nb) {
            const int cb = nw * 32 + nb * 8 + (lane & 3) * 2;
            const float2 bv = *(const float2*)&bias[col0 + cb];
            #pragma unroll
            for (int mb = 0; mb < 4; ++mb) {
                const int rr = mw * 64 + mb * 16 + (lane >> 2);
                *(float2*)&zs[rr * 132 + cb] =
                    make_float2(acc[mb][nb][0] + bv.x, acc[mb][nb][1] + bv.y);
                *(float2*)&zs[(rr + 8) * 132 + cb] =
                    make_float2(acc[mb][nb][2] + bv.x, acc[mb][nb][3] + bv.y);
            }
        }
        __syncthreads();
        #pragma unroll
        for (int it = 0; it < 16; ++it) {
            const int idx = tid + it * 256;           // 4096 float4 slots
            const int rr = idx >> 5, c4 = (idx & 31) * 4;
            float4 v = *(float4*)&zs[rr * 132 + c4];
            *(float4*)&Z[(size_t)(row0 + rr) * D + col0 + c4] = v;
        }
    } else {
        // ---- VQ epilogue: score = tvec[code] - 2*dot ; argmin ; gather
        #pragma unroll
        for (int mb = 0; mb < 4; ++mb) {
            #pragma unroll
            for (int rh = 0; rh < 2; ++rh) {
                ull best = ~0ull;
                #pragma unroll
                for (int nb = 0; nb < 4; ++nb) {
                    #pragma unroll
                    for (int j = 0; j < 2; ++j) {
                        const int code = nw * 32 + nb * 8 + (lane & 3) * 2 + j;
                        const float sc = fmaf(-2.f, acc[mb][nb][rh * 2 + j], scn[code]);
                        u32 o = __float_as_uint(sc);
                        o = (o & 0x80000000u) ? ~o : (o | 0x80000000u);
                        const ull key = ((ull)o << 32) | (u32)code;
                        if (key < best) best = key;
                    }
                }
                ull t = __shfl_xor_sync(0xffffffffu, best, 1); if (t < best) best = t;
                t     = __shfl_xor_sync(0xffffffffu, best, 2); if (t < best) best = t;
                const int rowl = mw * 64 + mb * 16 + rh * 8 + (lane >> 2);
                if ((lane & 3) == 0) wb[rowl * 4 + nw] = best;
            }
        }
        __syncthreads();

        if (tid < 128) {
            ull m = wb[tid * 4];
            ull a = wb[tid * 4 + 1]; if (a < m) m = a;
            a = wb[tid * 4 + 2];     if (a < m) m = a;
            a = wb[tid * 4 + 3];     if (a < m) m = a;
            bidx[tid] = (int)(m & 0xffffffffu);
        }
        __syncthreads();

        for (int rr = w; rr < 128; rr += 8) {
            const int idx = bidx[rr];
            const float4* s4 = (const float4*)(CB + (size_t)idx * D);
            float4* o1 = (float4*)(Q1 + (size_t)(row0 + rr) * D);
            float4* o2 = (float4*)(Q2 + (size_t)(row0 + rr) * D);
            #pragma unroll
            for (int i = lane; i < D / 4; i += 32) {
                const float4 vv = s4[i];
                o1[i] = vv;
                o2[i] = vv;
            }
        }
    }
}

// ---------------------------------------------------------------- launcher
extern "C" void kernel_launch(void* const* d_in, const int* in_sizes, int n_in,
                              void* d_out, int out_size)
{
    const float* x  = (const float*)d_in[0];
    const float* W  = (const float*)d_in[1];
    const float* b  = (const float*)d_in[2];
    const float* cb = (const float*)d_in[3];

    const int M = in_sizes[0] / D;            // 32768

    float* out = (float*)d_out;
    float* q1 = out;
    float* q2 = out + (size_t)M * D;
    float* z  = out + (size_t)2 * M * D;

    prepass1_kernel<<<128 + (M / 128) * 8, 256>>>(x, W, cb);
    prepass2_kernel<<<17, 256>>>(b, cb);

    cudaFuncSetAttribute(fused_hmma, cudaFuncAttributeMaxDynamicSharedMemorySize, FUSED_SMEM);
    fused_hmma<<<dim3(5, M / 128), 256, FUSED_SMEM>>>(b, cb, z, q1, q2);
}

// round 13
// speedup vs baseline: 1.4422x; 1.4422x over previous
#include <cuda_runtime.h>
#include <cuda_fp16.h>
#include <cstdint>
#include <cstddef>

#define DEVINL __device__ __forceinline__
using u32 = uint32_t;
using ull = unsigned long long;

constexpr int D  = 512;
constexpr int NC = 128;

constexpr int TILE_B   = 16384;            // one 128-row x 128B packed tile (hi|lo)
constexpr int STAGE_B  = 2 * TILE_B;       // A tile + B tile
constexpr int NSTAGE   = 3;
constexpr int LOOP_SMEM = NSTAGE * STAGE_B;            // 98304
constexpr int FUSED_SMEM = LOOP_SMEM + 512 + 4096 + 512;  // + tvec + wb + bidx

__device__ float g_tvec[NC];               // ||c||^2 - 2 b.c
__device__ __align__(128) char g_xsplit[256][16][TILE_B];   // 64 MB
__device__ __align__(128) char g_wsplit[4][16][TILE_B];     // 1 MB
__device__ __align__(128) char g_esplit[16][TILE_B];        // 256 KB (E = CB@W, split)

// ---------------------------------------------------------------- helpers
DEVINL u32 smem_u32(const void* p) {
    u32 a;
    asm("{ .reg .u64 t; cvta.to.shared.u64 t, %1; cvt.u32.u64 %0, t; }"
        : "=r"(a) : "l"(p));
    return a;
}
DEVINL void ldsm4(u32& r0, u32& r1, u32& r2, u32& r3, u32 a) {
    asm volatile("ldmatrix.sync.aligned.m8n8.x4.shared.b16 {%0,%1,%2,%3}, [%4];"
                 : "=r"(r0), "=r"(r1), "=r"(r2), "=r"(r3) : "r"(a));
}
DEVINL void mma_f16(float c[4], const u32 a[4], const u32 b[2]) {
    asm volatile(
        "mma.sync.aligned.m16n8k16.row.col.f32.f16.f16.f32 "
        "{%0,%1,%2,%3},{%4,%5,%6,%7},{%8,%9},{%0,%1,%2,%3};"
        : "+f"(c[0]), "+f"(c[1]), "+f"(c[2]), "+f"(c[3])
        : "r"(a[0]), "r"(a[1]), "r"(a[2]), "r"(a[3]), "r"(b[0]), "r"(b[1]));
}
DEVINL u32 pack_h2(__half a, __half b) {
    __half2 h = __halves2half2(a, b);
    return *reinterpret_cast<u32*>(&h);
}
DEVINL void fsplit(float x, __half& h, __half& l) {
    h = __float2half_rn(x);
    l = __float2half_rn(x - __half2float(h));
}
DEVINL void cp16(u32 dst, const void* src) {
    asm volatile("cp.async.cg.shared.global [%0], [%1], 16;" :: "r"(dst), "l"(src));
}
DEVINL void cp_commit() { asm volatile("cp.async.commit_group;" ::: "memory"); }
DEVINL void cp_wait1()  { asm volatile("cp.async.wait_group 1;" ::: "memory"); }
DEVINL void cp_wait0()  { asm volatile("cp.async.wait_group 0;" ::: "memory"); }

// split 16 fp32 into 2 hi + 2 lo 16B chunks of a packed tile row.
// hi chunk c at ((c^e)<<4), lo at (((c^4)^e)<<4), e = row&7.
DEVINL void split16(const float4 v[4], char* drow, int c0, int e) {
    #pragma unroll
    for (int c2 = 0; c2 < 2; ++c2) {
        const float f[8] = { v[2*c2].x, v[2*c2].y, v[2*c2].z, v[2*c2].w,
                             v[2*c2+1].x, v[2*c2+1].y, v[2*c2+1].z, v[2*c2+1].w };
        __half hh[8], ll[8];
        #pragma unroll
        for (int j = 0; j < 8; ++j) fsplit(f[j], hh[j], ll[j]);
        uint4 uh = make_uint4(pack_h2(hh[0], hh[1]), pack_h2(hh[2], hh[3]),
                              pack_h2(hh[4], hh[5]), pack_h2(hh[6], hh[7]));
        uint4 ul = make_uint4(pack_h2(ll[0], ll[1]), pack_h2(ll[2], ll[3]),
                              pack_h2(ll[4], ll[5]), pack_h2(ll[6], ll[7]));
        const int c = c0 + c2;
        *(uint4*)(drow + (((c)     ^ e) << 4)) = uh;
        *(uint4*)(drow + (((c ^ 4) ^ e) << 4)) = ul;
    }
}

// ---------------------------------------------------------------- prepass (single launch)
// b<16: E strip compute+split (self-contained). b==16: tvec.
// [17,81): W tiles. [81,81+4096): X tiles.
__global__ void prepass_kernel(const float* __restrict__ X,
                               const float* __restrict__ W,
                               const float* __restrict__ B,
                               const float* __restrict__ CB) {
    __shared__ __align__(16) char st[TILE_B];     // 16 KB, all block types
    __shared__ float ws[1024];                    // 4 KB (E blocks: W chunk)
    const int b = blockIdx.x;
    const int tid = threadIdx.x;
    const int lane = tid & 31, w = tid >> 5;

    if (b < 16) {
        // E[:, c0:c0+32] = CB(128x512) @ W(512x512) strip.
        // warp w owns rows w*16..w*16+15; lane owns col c0+lane. 16 acc/thread.
        const int c0 = b * 32;
        float* cbs = (float*)st;                  // CB chunk [128 rows][32 k]
        float acc[16];
        #pragma unroll
        for (int i = 0; i < 16; ++i) acc[i] = 0.f;
        const int r0 = w * 16;

        for (int kc = 0; kc < 16; ++kc) {
            const int k0 = kc * 32;
            __syncthreads();
            {   // load CB chunk: thread -> row tid>>1, 16 floats at k0 + (tid&1)*16
                const int rr = tid >> 1, hh = tid & 1;
                const float4* src = (const float4*)(CB + (size_t)rr * D + k0 + hh * 16);
                float4* dstv = (float4*)(cbs + rr * 32 + hh * 16);
                #pragma unroll
                for (int i = 0; i < 4; ++i) dstv[i] = src[i];
            }
            {   // load W chunk: 32 k-rows x 32 cols; thread loads 16B
                const int kr = tid >> 3, co = (tid & 7) * 4;
                *(float4*)(ws + kr * 32 + co) =
                    *(const float4*)(W + (size_t)(k0 + kr) * D + c0 + co);
            }
            __syncthreads();
            #pragma unroll 8
            for (int k = 0; k < 32; ++k) {
                const float wv = ws[k * 32 + lane];
                #pragma unroll
                for (int i = 0; i < 16; ++i)
                    acc[i] = fmaf(cbs[(r0 + i) * 32 + k], wv, acc[i]);
            }
        }
        __syncthreads();
        // transpose accumulators into st as fp32 [row][32 cols]
        float* es = (float*)st;
        #pragma unroll
        for (int i = 0; i < 16; ++i) es[(r0 + i) * 32 + lane] = acc[i];
        __syncthreads();
        // split row-wise straight to g_esplit[b] (small, scattered STG OK)
        const int rr = tid >> 1, hh = tid & 1, e = rr & 7;
        float4 v[4];
        #pragma unroll
        for (int i = 0; i < 4; ++i) v[i] = *(float4*)(es + rr * 32 + hh * 16 + i * 4);
        split16(v, &g_esplit[b][rr * 128], hh * 2, e);
        return;
    }
    if (b == 16) {
        const int c = tid >> 1, h = tid & 1;
        const float* cp = CB + (size_t)c * D + h * 256;
        const float* bp = B + h * 256;
        float s2 = 0.f, sb = 0.f;
        #pragma unroll 4
        for (int k = 0; k < 64; ++k) {
            float4 v = ((const float4*)cp)[k];
            float4 bv = ((const float4*)bp)[k];
            s2 += v.x * v.x + v.y * v.y + v.z * v.z + v.w * v.w;
            sb += v.x * bv.x + v.y * bv.y + v.z * bv.z + v.w * bv.w;
        }
        s2 += __shfl_xor_sync(0xffffffffu, s2, 1);
        sb += __shfl_xor_sync(0xffffffffu, sb, 1);
        if (!h) g_tvec[c] = s2 - 2.f * sb;
        return;
    }

    // W / X tile split (R8 layout: 16KB smem, 1 slice per block)
    const int r = tid >> 1, h = tid & 1, e = r & 7;
    const float* src0;
    char* dst;
    if (b < 81) {
        const int bb = b - 17;
        const int ct = bb >> 4, s = bb & 15;
        src0 = W + (size_t)(ct * 128 + r) * D + s * 32 + h * 16;
        dst = &g_wsplit[ct][s][0];
    } else {
        const int bb = b - 81;
        const int rb = bb >> 4, s = bb & 15;
        src0 = X + (size_t)(rb * 128 + r) * D + s * 32 + h * 16;
        dst = &g_xsplit[rb][s][0];
    }
    float4 v[4];
    #pragma unroll
    for (int i = 0; i < 4; ++i) v[i] = ((const float4*)src0)[i];
    split16(v, &st[r * 128], h * 2, e);
    __syncthreads();
    #pragma unroll
    for (int k = 0; k < 4; ++k)
        *(uint4*)(dst + tid * 16 + k * 4096) = *(const uint4*)(st + tid * 16 + k * 4096);
}

// ---------------------------------------------------------------- per-stage MMA (128x128x32, split-2)
DEVINL void stage_mma(u32 aT, int tid, float acc[4][4][4]) {
    const int lane = tid & 31, w = tid >> 5;
    const int mw = w >> 2, nw = w & 3;
    const int eL = lane & 7;
    const int rA = lane & 15, cAk = lane >> 4;
    const int rB0 = nw * 32 + ((lane >> 4) << 3) + (lane & 7);
    const int cBk = (lane >> 3) & 1;
    const u32 bT = aT + TILE_B;

    #pragma unroll
    for (int kk = 0; kk < 2; ++kk) {
        u32 ahi[4][4], alo[4][4], bhi[4][2], blo[4][2];
        const int swA = (kk * 2 + cAk) ^ eL;
        #pragma unroll
        for (int mb = 0; mb < 4; ++mb) {
            const u32 base = aT + (mw * 64 + mb * 16 + rA) * 128;
            ldsm4(ahi[mb][0], ahi[mb][1], ahi[mb][2], ahi[mb][3], base + (swA << 4));
            ldsm4(alo[mb][0], alo[mb][1], alo[mb][2], alo[mb][3], base + ((swA ^ 4) << 4));
        }
        const int swB = (kk * 2 + cBk) ^ eL;
        #pragma unroll
        for (int bp = 0; bp < 2; ++bp) {
            const u32 base = bT + (rB0 + bp * 16) * 128;
            u32 r0, r1, r2, r3;
            ldsm4(r0, r1, r2, r3, base + (swB << 4));
            bhi[bp*2][0] = r0; bhi[bp*2][1] = r1;
            bhi[bp*2+1][0] = r2; bhi[bp*2+1][1] = r3;
            ldsm4(r0, r1, r2, r3, base + ((swB ^ 4) << 4));
            blo[bp*2][0] = r0; blo[bp*2][1] = r1;
            blo[bp*2+1][0] = r2; blo[bp*2+1][1] = r3;
        }
        #pragma unroll
        for (int mb = 0; mb < 4; ++mb)
            #pragma unroll
            for (int nb = 0; nb < 4; ++nb) {
                mma_f16(acc[mb][nb], ahi[mb], bhi[nb]);
                mma_f16(acc[mb][nb], ahi[mb], blo[nb]);
                mma_f16(acc[mb][nb], alo[mb], bhi[nb]);
            }
    }
}

// ---------------------------------------------------------------- fused GEMM + VQ
// grid (5, 256): ct<4 -> Z tile epilogue; ct==4 -> B=E, argmin + gather epilogue.
__global__ void __launch_bounds__(256, 2)
fused_hmma(const float* __restrict__ bias, const float* __restrict__ CB,
           float* __restrict__ Z, float* __restrict__ Q1, float* __restrict__ Q2)
{
    extern __shared__ char smc[];
    float* scn  = (float*)(smc + LOOP_SMEM);
    ull*   wb   = (ull*)  (smc + LOOP_SMEM + 512);
    int*   bidx = (int*)  (smc + LOOP_SMEM + 512 + 4096);

    const u32 sb = smem_u32(smc);
    const int tid = threadIdx.x;
    const int ct = blockIdx.x, rb = blockIdx.y;      // ct fast -> X L2 reuse
    const int li = tid & 127;

    if (ct == 4 && tid < NC) scn[tid] = g_tvec[tid];

    const char* srcBase = (tid < 128) ? &g_xsplit[rb][0][0]
                        : (ct < 4 ? &g_wsplit[ct][0][0] : &g_esplit[0][0]);
    const u32 dstBase = ((tid < 128) ? 0u : (u32)TILE_B) + li * 16;

    #define F_ISSUE(s, buf) do {                                              \
        const char* _src = srcBase + (s) * TILE_B + li * 16;                  \
        const u32 _d = sb + (buf) * STAGE_B + dstBase;                        \
        _Pragma("unroll")                                                     \
        for (int _k = 0; _k < 8; ++_k) cp16(_d + _k * 2048, _src + _k * 2048);\
    } while (0)

    F_ISSUE(0, 0); cp_commit();
    F_ISSUE(1, 1); cp_commit();

    float acc[4][4][4] = {};
    int buf = 0;
    #pragma unroll 1
    for (int s = 0; s < 16; ++s) {
        cp_wait1();
        __syncthreads();
        int b2 = buf + 2; if (b2 >= 3) b2 -= 3;
        if (s + 2 < 16) F_ISSUE(s + 2, b2);
        cp_commit();
        stage_mma(sb + buf * STAGE_B, tid, acc);
        if (++buf == 3) buf = 0;
    }
    #undef F_ISSUE

    cp_wait0();
    __syncthreads();

    const int lane = tid & 31, w = tid >> 5;
    const int mw = w >> 2, nw = w & 3;
    const int row0 = rb * 128;

    if (ct < 4) {
        // ---- Z epilogue: stage in smem, add bias, coalesced fp32 store
        float* zs = (float*)smc;                      // [128][132] = 67584 B
        const int col0 = ct * 128;
        #pragma unroll
        for (int nb = 0; nb < 4; ++nb) {
            const int cb = nw * 32 + nb * 8 + (lane & 3) * 2;
            const float2 bv = *(const float2*)&bias[col0 + cb];
            #pragma unroll
            for (int mb = 0; mb < 4; ++mb) {
                const int rr = mw * 64 + mb * 16 + (lane >> 2);
                *(float2*)&zs[rr * 132 + cb] =
                    make_float2(acc[mb][nb][0] + bv.x, acc[mb][nb][1] + bv.y);
                *(float2*)&zs[(rr + 8) * 132 + cb] =
                    make_float2(acc[mb][nb][2] + bv.x, acc[mb][nb][3] + bv.y);
            }
        }
        __syncthreads();
        #pragma unroll
        for (int it = 0; it < 16; ++it) {
            const int idx = tid + it * 256;           // 4096 float4 slots
            const int rr = idx >> 5, c4 = (idx & 31) * 4;
            float4 v = *(float4*)&zs[rr * 132 + c4];
            *(float4*)&Z[(size_t)(row0 + rr) * D + col0 + c4] = v;
        }
    } else {
        // ---- VQ epilogue: score = tvec[code] - 2*dot ; argmin ; gather
        #pragma unroll
        for (int mb = 0; mb < 4; ++mb) {
            #pragma unroll
            for (int rh = 0; rh < 2; ++rh) {
                ull best = ~0ull;
                #pragma unroll
                for (int nb = 0; nb < 4; ++nb) {
                    #pragma unroll
                    for (int j = 0; j < 2; ++j) {
                        const int code = nw * 32 + nb * 8 + (lane & 3) * 2 + j;
                        const float sc = fmaf(-2.f, acc[mb][nb][rh * 2 + j], scn[code]);
                        u32 o = __float_as_uint(sc);
                        o = (o & 0x80000000u) ? ~o : (o | 0x80000000u);
                        const ull key = ((ull)o << 32) | (u32)code;
                        if (key < best) best = key;
                    }
                }
                ull t = __shfl_xor_sync(0xffffffffu, best, 1); if (t < best) best = t;
                t     = __shfl_xor_sync(0xffffffffu, best, 2); if (t < best) best = t;
                const int rowl = mw * 64 + mb * 16 + rh * 8 + (lane >> 2);
                if ((lane & 3) == 0) wb[rowl * 4 + nw] = best;
            }
        }
        __syncthreads();

        if (tid < 128) {
            ull m = wb[tid * 4];
            ull a = wb[tid * 4 + 1]; if (a < m) m = a;
            a = wb[tid * 4 + 2];     if (a < m) m = a;
            a = wb[tid * 4 + 3];     if (a < m) m = a;
            bidx[tid] = (int)(m & 0xffffffffu);
        }
        __syncthreads();

        for (int rr = w; rr < 128; rr += 8) {
            const int idx = bidx[rr];
            const float4* s4 = (const float4*)(CB + (size_t)idx * D);
            float4* o1 = (float4*)(Q1 + (size_t)(row0 + rr) * D);
            float4* o2 = (float4*)(Q2 + (size_t)(row0 + rr) * D);
            #pragma unroll
            for (int i = lane; i < D / 4; i += 32) {
                const float4 vv = s4[i];
                o1[i] = vv;
                o2[i] = vv;
            }
        }
    }
}

// ---------------------------------------------------------------- launcher
extern "C" void kernel_launch(void* const* d_in, const int* in_sizes, int n_in,
                              void* d_out, int out_size)
{
    const float* x  = (const float*)d_in[0];
    const float* W  = (const float*)d_in[1];
    const float* b  = (const float*)d_in[2];
    const float* cb = (const float*)d_in[3];

    const int M = in_sizes[0] / D;            // 32768

    float* out = (float*)d_out;
    float* q1 = out;
    float* q2 = out + (size_t)M * D;
    float* z  = out + (size_t)2 * M * D;

    prepass_kernel<<<81 + (M / 128) * 16, 256>>>(x, W, b, cb);

    cudaFuncSetAttribute(fused_hmma, cudaFuncAttributeMaxDynamicSharedMemorySize, FUSED_SMEM);
    fused_hmma<<<dim3(5, M / 128), 256, FUSED_SMEM>>>(b, cb, z, q1, q2);
}

// round 14
// speedup vs baseline: 1.4980x; 1.0387x over previous
#include <cuda_runtime.h>
#include <cuda_fp16.h>
#include <cstdint>
#include <cstddef>

#define DEVINL __device__ __forceinline__
using u32 = uint32_t;
using ull = unsigned long long;

constexpr int D  = 512;
constexpr int NC = 128;

constexpr int TILE_B   = 16384;            // one 128-row x 128B packed tile (hi|lo)
constexpr int STAGE_B  = 2 * TILE_B;       // A tile + B tile
constexpr int NSTAGE   = 3;
constexpr int LOOP_SMEM = NSTAGE * STAGE_B;            // 98304
constexpr int FUSED_SMEM = LOOP_SMEM + 512 + 4096 + 512;  // + tvec + wb + bidx

constexpr int CBP = 36;                    // padded CB row stride (floats), 144B = 9x16B

__device__ float g_tvec[NC];               // ||c||^2 - 2 b.c
__device__ __align__(128) char g_xsplit[256][16][TILE_B];   // 64 MB
__device__ __align__(128) char g_wsplit[4][16][TILE_B];     // 1 MB
__device__ __align__(128) char g_esplit[16][TILE_B];        // 256 KB (E = CB@W, split)

// ---------------------------------------------------------------- helpers
DEVINL u32 smem_u32(const void* p) {
    u32 a;
    asm("{ .reg .u64 t; cvta.to.shared.u64 t, %1; cvt.u32.u64 %0, t; }"
        : "=r"(a) : "l"(p));
    return a;
}
DEVINL void ldsm4(u32& r0, u32& r1, u32& r2, u32& r3, u32 a) {
    asm volatile("ldmatrix.sync.aligned.m8n8.x4.shared.b16 {%0,%1,%2,%3}, [%4];"
                 : "=r"(r0), "=r"(r1), "=r"(r2), "=r"(r3) : "r"(a));
}
DEVINL void mma_f16(float c[4], const u32 a[4], const u32 b[2]) {
    asm volatile(
        "mma.sync.aligned.m16n8k16.row.col.f32.f16.f16.f32 "
        "{%0,%1,%2,%3},{%4,%5,%6,%7},{%8,%9},{%0,%1,%2,%3};"
        : "+f"(c[0]), "+f"(c[1]), "+f"(c[2]), "+f"(c[3])
        : "r"(a[0]), "r"(a[1]), "r"(a[2]), "r"(a[3]), "r"(b[0]), "r"(b[1]));
}
DEVINL u32 pack_h2(__half a, __half b) {
    __half2 h = __halves2half2(a, b);
    return *reinterpret_cast<u32*>(&h);
}
DEVINL void fsplit(float x, __half& h, __half& l) {
    h = __float2half_rn(x);
    l = __float2half_rn(x - __half2float(h));
}
DEVINL void cp16(u32 dst, const void* src) {
    asm volatile("cp.async.cg.shared.global [%0], [%1], 16;" :: "r"(dst), "l"(src));
}
DEVINL void cp_commit() { asm volatile("cp.async.commit_group;" ::: "memory"); }
DEVINL void cp_wait1()  { asm volatile("cp.async.wait_group 1;" ::: "memory"); }
DEVINL void cp_wait0()  { asm volatile("cp.async.wait_group 0;" ::: "memory"); }

// split 16 fp32 into 2 hi + 2 lo 16B chunks of a packed tile row.
// hi chunk c at ((c^e)<<4), lo at (((c^4)^e)<<4), e = row&7.
DEVINL void split16(const float4 v[4], char* drow, int c0, int e) {
    #pragma unroll
    for (int c2 = 0; c2 < 2; ++c2) {
        const float f[8] = { v[2*c2].x, v[2*c2].y, v[2*c2].z, v[2*c2].w,
                             v[2*c2+1].x, v[2*c2+1].y, v[2*c2+1].z, v[2*c2+1].w };
        __half hh[8], ll[8];
        #pragma unroll
        for (int j = 0; j < 8; ++j) fsplit(f[j], hh[j], ll[j]);
        uint4 uh = make_uint4(pack_h2(hh[0], hh[1]), pack_h2(hh[2], hh[3]),
                              pack_h2(hh[4], hh[5]), pack_h2(hh[6], hh[7]));
        uint4 ul = make_uint4(pack_h2(ll[0], ll[1]), pack_h2(ll[2], ll[3]),
                              pack_h2(ll[4], ll[5]), pack_h2(ll[6], ll[7]));
        const int c = c0 + c2;
        *(uint4*)(drow + (((c)     ^ e) << 4)) = uh;
        *(uint4*)(drow + (((c ^ 4) ^ e) << 4)) = ul;
    }
}

// ---------------------------------------------------------------- prepass (single launch)
// b<32: E sub-strip compute+split (64 rows x 32 cols each). b==32: tvec.
// [33,97): W tiles. [97,97+4096): X tiles.
__global__ void prepass_kernel(const float* __restrict__ X,
                               const float* __restrict__ W,
                               const float* __restrict__ B,
                               const float* __restrict__ CB) {
    __shared__ __align__(16) char st[TILE_B + 2048];  // 18.4 KB: tiles use 16KB; E uses 64xCBP fp32
    __shared__ float ws[1024];                         // 4 KB (E blocks: W chunk)
    const int b = blockIdx.x;
    const int tid = threadIdx.x;
    const int lane = tid & 31, w = tid >> 5;

    if (b < 32) {
        // E[r0g..r0g+64, c0..c0+32] = CB rows @ W cols.
        // warp w owns 8 rows; lane owns one col. 8 acc/thread.
        const int c0 = (b >> 1) * 32;
        const int rg = (b & 1) * 64;                  // global row base of this block
        float* cbs = (float*)st;                      // CB chunk [64 rows][CBP]
        float acc[8];
        #pragma unroll
        for (int i = 0; i < 8; ++i) acc[i] = 0.f;
        const int r0 = w * 8;                         // local row base of this warp

        for (int kc = 0; kc < 16; ++kc) {
            const int k0 = kc * 32;
            __syncthreads();
            {   // load CB chunk: 64 rows x 32 k; thread -> row tid>>2, 8 floats
                const int rr = tid >> 2, q = tid & 3;
                const float4* src = (const float4*)(CB + (size_t)(rg + rr) * D + k0 + q * 8);
                float4* dstv = (float4*)(cbs + rr * CBP + q * 8);
                dstv[0] = src[0];
                dstv[1] = src[1];
            }
            {   // load W chunk: 32 k-rows x 32 cols
                const int kr = tid >> 3, co = (tid & 7) * 4;
                *(float4*)(ws + kr * 32 + co) =
                    *(const float4*)(W + (size_t)(k0 + kr) * D + c0 + co);
            }
            __syncthreads();
            #pragma unroll 2
            for (int k4 = 0; k4 < 8; ++k4) {
                const int k = k4 * 4;
                float wv0 = ws[(k + 0) * 32 + lane];
                float wv1 = ws[(k + 1) * 32 + lane];
                float wv2 = ws[(k + 2) * 32 + lane];
                float wv3 = ws[(k + 3) * 32 + lane];
                #pragma unroll
                for (int i = 0; i < 8; ++i) {
                    const float4 cv = *(const float4*)(cbs + (r0 + i) * CBP + k);  // broadcast
                    acc[i] = fmaf(cv.x, wv0, acc[i]);
                    acc[i] = fmaf(cv.y, wv1, acc[i]);
                    acc[i] = fmaf(cv.z, wv2, acc[i]);
                    acc[i] = fmaf(cv.w, wv3, acc[i]);
                }
            }
        }
        __syncthreads();
        // write accumulators to es [64 local rows][stride CBP], cols = lane
        float* es = (float*)st;
        #pragma unroll
        for (int i = 0; i < 8; ++i) es[(r0 + i) * CBP + lane] = acc[i];
        __syncthreads();
        // split: threads 0..127 -> (local row, half); write to g_esplit[col slice]
        if (tid < 128) {
            const int rl = tid >> 1, hh = tid & 1;
            const int grow = rg + rl;
            const int e = grow & 7;
            float4 v[4];
            #pragma unroll
            for (int i = 0; i < 4; ++i) v[i] = *(float4*)(es + rl * CBP + hh * 16 + i * 4);
            split16(v, &g_esplit[b >> 1][grow * 128], hh * 2, e);
        }
        return;
    }
    if (b == 32) {
        const int c = tid >> 1, h = tid & 1;
        const float* cp = CB + (size_t)c * D + h * 256;
        const float* bp = B + h * 256;
        float s2 = 0.f, sb = 0.f;
        #pragma unroll 4
        for (int k = 0; k < 64; ++k) {
            float4 v = ((const float4*)cp)[k];
            float4 bv = ((const float4*)bp)[k];
            s2 += v.x * v.x + v.y * v.y + v.z * v.z + v.w * v.w;
            sb += v.x * bv.x + v.y * bv.y + v.z * bv.z + v.w * bv.w;
        }
        s2 += __shfl_xor_sync(0xffffffffu, s2, 1);
        sb += __shfl_xor_sync(0xffffffffu, sb, 1);
        if (!h) g_tvec[c] = s2 - 2.f * sb;
        return;
    }

    // W / X tile split (R8 layout: 16KB of st, 1 slice per block)
    const int r = tid >> 1, h = tid & 1, e = r & 7;
    const float* src0;
    char* dst;
    if (b < 97) {
        const int bb = b - 33;
        const int ct = bb >> 4, s = bb & 15;
        src0 = W + (size_t)(ct * 128 + r) * D + s * 32 + h * 16;
        dst = &g_wsplit[ct][s][0];
    } else {
        const int bb = b - 97;
        const int rb = bb >> 4, s = bb & 15;
        src0 = X + (size_t)(rb * 128 + r) * D + s * 32 + h * 16;
        dst = &g_xsplit[rb][s][0];
    }
    float4 v[4];
    #pragma unroll
    for (int i = 0; i < 4; ++i) v[i] = ((const float4*)src0)[i];
    split16(v, &st[r * 128], h * 2, e);
    __syncthreads();
    #pragma unroll
    for (int k = 0; k < 4; ++k)
        *(uint4*)(dst + tid * 16 + k * 4096) = *(const uint4*)(st + tid * 16 + k * 4096);
}

// ---------------------------------------------------------------- per-stage MMA (128x128x32, split-2)
DEVINL void stage_mma(u32 aT, int tid, float acc[4][4][4]) {
    const int lane = tid & 31, w = tid >> 5;
    const int mw = w >> 2, nw = w & 3;
    const int eL = lane & 7;
    const int rA = lane & 15, cAk = lane >> 4;
    const int rB0 = nw * 32 + ((lane >> 4) << 3) + (lane & 7);
    const int cBk = (lane >> 3) & 1;
    const u32 bT = aT + TILE_B;

    #pragma unroll
    for (int kk = 0; kk < 2; ++kk) {
        u32 ahi[4][4], alo[4][4], bhi[4][2], blo[4][2];
        const int swA = (kk * 2 + cAk) ^ eL;
        #pragma unroll
        for (int mb = 0; mb < 4; ++mb) {
            const u32 base = aT + (mw * 64 + mb * 16 + rA) * 128;
            ldsm4(ahi[mb][0], ahi[mb][1], ahi[mb][2], ahi[mb][3], base + (swA << 4));
            ldsm4(alo[mb][0], alo[mb][1], alo[mb][2], alo[mb][3], base + ((swA ^ 4) << 4));
        }
        const int swB = (kk * 2 + cBk) ^ eL;
        #pragma unroll
        for (int bp = 0; bp < 2; ++bp) {
            const u32 base = bT + (rB0 + bp * 16) * 128;
            u32 r0, r1, r2, r3;
            ldsm4(r0, r1, r2, r3, base + (swB << 4));
            bhi[bp*2][0] = r0; bhi[bp*2][1] = r1;
            bhi[bp*2+1][0] = r2; bhi[bp*2+1][1] = r3;
            ldsm4(r0, r1, r2, r3, base + ((swB ^ 4) << 4));
            blo[bp*2][0] = r0; blo[bp*2][1] = r1;
            blo[bp*2+1][0] = r2; blo[bp*2+1][1] = r3;
        }
        #pragma unroll
        for (int mb = 0; mb < 4; ++mb)
            #pragma unroll
            for (int nb = 0; nb < 4; ++nb) {
                mma_f16(acc[mb][nb], ahi[mb], bhi[nb]);
                mma_f16(acc[mb][nb], ahi[mb], blo[nb]);
                mma_f16(acc[mb][nb], alo[mb], bhi[nb]);
            }
    }
}

// ---------------------------------------------------------------- fused GEMM + VQ
// grid (5, 256): ct<4 -> Z tile epilogue; ct==4 -> B=E, argmin + gather epilogue.
__global__ void __launch_bounds__(256, 2)
fused_hmma(const float* __restrict__ bias, const float* __restrict__ CB,
           float* __restrict__ Z, float* __restrict__ Q1, float* __restrict__ Q2)
{
    extern __shared__ char smc[];
    float* scn  = (float*)(smc + LOOP_SMEM);
    ull*   wb   = (ull*)  (smc + LOOP_SMEM + 512);
    int*   bidx = (int*)  (smc + LOOP_SMEM + 512 + 4096);

    const u32 sb = smem_u32(smc);
    const int tid = threadIdx.x;
    const int ct = blockIdx.x, rb = blockIdx.y;      // ct fast -> X L2 reuse
    const int li = tid & 127;

    if (ct == 4 && tid < NC) scn[tid] = g_tvec[tid];

    const char* srcBase = (tid < 128) ? &g_xsplit[rb][0][0]
                        : (ct < 4 ? &g_wsplit[ct][0][0] : &g_esplit[0][0]);
    const u32 dstBase = ((tid < 128) ? 0u : (u32)TILE_B) + li * 16;

    #define F_ISSUE(s, buf) do {                                              \
        const char* _src = srcBase + (s) * TILE_B + li * 16;                  \
        const u32 _d = sb + (buf) * STAGE_B + dstBase;                        \
        _Pragma("unroll")                                                     \
        for (int _k = 0; _k < 8; ++_k) cp16(_d + _k * 2048, _src + _k * 2048);\
    } while (0)

    F_ISSUE(0, 0); cp_commit();
    F_ISSUE(1, 1); cp_commit();

    float acc[4][4][4] = {};
    int buf = 0;
    #pragma unroll 1
    for (int s = 0; s < 16; ++s) {
        cp_wait1();
        __syncthreads();
        int b2 = buf + 2; if (b2 >= 3) b2 -= 3;
        if (s + 2 < 16) F_ISSUE(s + 2, b2);
        cp_commit();
        stage_mma(sb + buf * STAGE_B, tid, acc);
        if (++buf == 3) buf = 0;
    }
    #undef F_ISSUE

    cp_wait0();
    __syncthreads();

    const int lane = tid & 31, w = tid >> 5;
    const int mw = w >> 2, nw = w & 3;
    const int row0 = rb * 128;

    if (ct < 4) {
        // ---- Z epilogue: stage in smem, add bias, coalesced fp32 store
        float* zs = (float*)smc;                      // [128][132] = 67584 B
        const int col0 = ct * 128;
        #pragma unroll
        for (int nb = 0; nb < 4; ++nb) {
            const int cb = nw * 32 + nb * 8 + (lane & 3) * 2;
            const float2 bv = *(const float2*)&bias[col0 + cb];
            #pragma unroll
            for (int mb = 0; mb < 4; ++mb) {
                const int rr = mw * 64 + mb * 16 + (lane >> 2);
                *(float2*)&zs[rr * 132 + cb] =
                    make_float2(acc[mb][nb][0] + bv.x, acc[mb][nb][1] + bv.y);
                *(float2*)&zs[(rr + 8) * 132 + cb] =
                    make_float2(acc[mb][nb][2] + bv.x, acc[mb][nb][3] + bv.y);
            }
        }
        __syncthreads();
        #pragma unroll
        for (int it = 0; it < 16; ++it) {
            const int idx = tid + it * 256;           // 4096 float4 slots
            const int rr = idx >> 5, c4 = (idx & 31) * 4;
            float4 v = *(float4*)&zs[rr * 132 + c4];
            *(float4*)&Z[(size_t)(row0 + rr) * D + col0 + c4] = v;
        }
    } else {
        // ---- VQ epilogue: score = tvec[code] - 2*dot ; argmin ; gather
        #pragma unroll
        for (int mb = 0; mb < 4; ++mb) {
            #pragma unroll
            for (int rh = 0; rh < 2; ++rh) {
                ull best = ~0ull;
                #pragma unroll
                for (int nb = 0; nb < 4; ++nb) {
                    #pragma unroll
                    for (int j = 0; j < 2; ++j) {
                        const int code = nw * 32 + nb * 8 + (lane & 3) * 2 + j;
                        const float sc = fmaf(-2.f, acc[mb][nb][rh * 2 + j], scn[code]);
                        u32 o = __float_as_uint(sc);
                        o = (o & 0x80000000u) ? ~o : (o | 0x80000000u);
                        const ull key = ((ull)o << 32) | (u32)code;
                        if (key < best) best = key;
                    }
                }
                ull t = __shfl_xor_sync(0xffffffffu, best, 1); if (t < best) best = t;
                t     = __shfl_xor_sync(0xffffffffu, best, 2); if (t < best) best = t;
                const int rowl = mw * 64 + mb * 16 + rh * 8 + (lane >> 2);
                if ((lane & 3) == 0) wb[rowl * 4 + nw] = best;
            }
        }
        __syncthreads();

        if (tid < 128) {
            ull m = wb[tid * 4];
            ull a = wb[tid * 4 + 1]; if (a < m) m = a;
            a = wb[tid * 4 + 2];     if (a < m) m = a;
            a = wb[tid * 4 + 3];     if (a < m) m = a;
            bidx[tid] = (int)(m & 0xffffffffu);
        }
        __syncthreads();

        for (int rr = w; rr < 128; rr += 8) {
            const int idx = bidx[rr];
            const float4* s4 = (const float4*)(CB + (size_t)idx * D);
            float4* o1 = (float4*)(Q1 + (size_t)(row0 + rr) * D);
            float4* o2 = (float4*)(Q2 + (size_t)(row0 + rr) * D);
            #pragma unroll
            for (int i = lane; i < D / 4; i += 32) {
                const float4 vv = s4[i];
                o1[i] = vv;
                o2[i] = vv;
            }
        }
    }
}

// ---------------------------------------------------------------- launcher
extern "C" void kernel_launch(void* const* d_in, const int* in_sizes, int n_in,
                              void* d_out, int out_size)
{
    const float* x  = (const float*)d_in[0];
    const float* W  = (const float*)d_in[1];
    const float* b  = (const float*)d_in[2];
    const float* cb = (const float*)d_in[3];

    const int M = in_sizes[0] / D;            // 32768

    float* out = (float*)d_out;
    float* q1 = out;
    float* q2 = out + (size_t)M * D;
    float* z  = out + (size_t)2 * M * D;

    prepass_kernel<<<97 + (M / 128) * 16, 256>>>(x, W, b, cb);

    cudaFuncSetAttribute(fused_hmma, cudaFuncAttributeMaxDynamicSharedMemorySize, FUSED_SMEM);
    fused_hmma<<<dim3(5, M / 128), 256, FUSED_SMEM>>>(b, cb, z, q1, q2);
}

// round 15
// speedup vs baseline: 1.4982x; 1.0002x over previous
#include <cuda_runtime.h>
#include <cuda_fp16.h>
#include <cstdint>
#include <cstddef>

#define DEVINL __device__ __forceinline__
using u32 = uint32_t;
using ull = unsigned long long;

constexpr int D  = 512;
constexpr int NC = 128;

constexpr int TILE_B   = 16384;            // one 128-row x 128B packed tile (hi|lo)
constexpr int STAGE_B  = 2 * TILE_B;       // A tile + B tile
constexpr int NSTAGE   = 3;
constexpr int LOOP_SMEM = NSTAGE * STAGE_B;            // 98304
constexpr int FUSED_SMEM = LOOP_SMEM + 512 + 4096 + 512;  // + tvec + wb + bidx

constexpr int CBP = 36;                    // padded CB row stride (floats), 144B = 9x16B

__device__ float g_tvec[NC];               // ||c||^2 - 2 b.c
__device__ __align__(128) char g_xsplit[256][16][TILE_B];   // 64 MB
__device__ __align__(128) char g_wsplit[4][16][TILE_B];     // 1 MB
__device__ __align__(128) char g_esplit[16][TILE_B];        // 256 KB (E = CB@W, split)

// ---------------------------------------------------------------- helpers
DEVINL u32 smem_u32(const void* p) {
    u32 a;
    asm("{ .reg .u64 t; cvta.to.shared.u64 t, %1; cvt.u32.u64 %0, t; }"
        : "=r"(a) : "l"(p));
    return a;
}
DEVINL void ldsm4(u32& r0, u32& r1, u32& r2, u32& r3, u32 a) {
    asm volatile("ldmatrix.sync.aligned.m8n8.x4.shared.b16 {%0,%1,%2,%3}, [%4];"
                 : "=r"(r0), "=r"(r1), "=r"(r2), "=r"(r3) : "r"(a));
}
DEVINL void mma_f16(float c[4], const u32 a[4], const u32 b[2]) {
    asm volatile(
        "mma.sync.aligned.m16n8k16.row.col.f32.f16.f16.f32 "
        "{%0,%1,%2,%3},{%4,%5,%6,%7},{%8,%9},{%0,%1,%2,%3};"
        : "+f"(c[0]), "+f"(c[1]), "+f"(c[2]), "+f"(c[3])
        : "r"(a[0]), "r"(a[1]), "r"(a[2]), "r"(a[3]), "r"(b[0]), "r"(b[1]));
}
DEVINL u32 pack_h2(__half a, __half b) {
    __half2 h = __halves2half2(a, b);
    return *reinterpret_cast<u32*>(&h);
}
DEVINL void fsplit(float x, __half& h, __half& l) {
    h = __float2half_rn(x);
    l = __float2half_rn(x - __half2float(h));
}
DEVINL void cp16(u32 dst, const void* src) {
    asm volatile("cp.async.cg.shared.global [%0], [%1], 16;" :: "r"(dst), "l"(src));
}
DEVINL void cp_commit() { asm volatile("cp.async.commit_group;" ::: "memory"); }
DEVINL void cp_wait1()  { asm volatile("cp.async.wait_group 1;" ::: "memory"); }
DEVINL void cp_wait0()  { asm volatile("cp.async.wait_group 0;" ::: "memory"); }

// split 16 fp32 into 2 hi + 2 lo 16B chunks of a packed tile row.
// hi chunk c at ((c^e)<<4), lo at (((c^4)^e)<<4), e = row&7.
DEVINL void split16(const float4 v[4], char* drow, int c0, int e) {
    #pragma unroll
    for (int c2 = 0; c2 < 2; ++c2) {
        const float f[8] = { v[2*c2].x, v[2*c2].y, v[2*c2].z, v[2*c2].w,
                             v[2*c2+1].x, v[2*c2+1].y, v[2*c2+1].z, v[2*c2+1].w };
        __half hh[8], ll[8];
        #pragma unroll
        for (int j = 0; j < 8; ++j) fsplit(f[j], hh[j], ll[j]);
        uint4 uh = make_uint4(pack_h2(hh[0], hh[1]), pack_h2(hh[2], hh[3]),
                              pack_h2(hh[4], hh[5]), pack_h2(hh[6], hh[7]));
        uint4 ul = make_uint4(pack_h2(ll[0], ll[1]), pack_h2(ll[2], ll[3]),
                              pack_h2(ll[4], ll[5]), pack_h2(ll[6], ll[7]));
        const int c = c0 + c2;
        *(uint4*)(drow + (((c)     ^ e) << 4)) = uh;
        *(uint4*)(drow + (((c ^ 4) ^ e) << 4)) = ul;
    }
}

// ---------------------------------------------------------------- prepass (single launch)
// b<32: E sub-strip compute+split (64 rows x 32 cols each). b==32: tvec.
// [33,97): W tiles. [97,97+4096): X tiles.
__global__ void prepass_kernel(const float* __restrict__ X,
                               const float* __restrict__ W,
                               const float* __restrict__ B,
                               const float* __restrict__ CB) {
    __shared__ __align__(16) char st[TILE_B + 2048];  // tiles use 16KB; E uses 64xCBP fp32
    __shared__ float ws[1024];                         // 4 KB (E blocks: W chunk)
    const int b = blockIdx.x;
    const int tid = threadIdx.x;
    const int lane = tid & 31, w = tid >> 5;

    if (b < 32) {
        const int c0 = (b >> 1) * 32;
        const int rg = (b & 1) * 64;
        float* cbs = (float*)st;                      // CB chunk [64 rows][CBP]
        float acc[8];
        #pragma unroll
        for (int i = 0; i < 8; ++i) acc[i] = 0.f;
        const int r0 = w * 8;

        for (int kc = 0; kc < 16; ++kc) {
            const int k0 = kc * 32;
            __syncthreads();
            {
                const int rr = tid >> 2, q = tid & 3;
                const float4* src = (const float4*)(CB + (size_t)(rg + rr) * D + k0 + q * 8);
                float4* dstv = (float4*)(cbs + rr * CBP + q * 8);
                dstv[0] = src[0];
                dstv[1] = src[1];
            }
            {
                const int kr = tid >> 3, co = (tid & 7) * 4;
                *(float4*)(ws + kr * 32 + co) =
                    *(const float4*)(W + (size_t)(k0 + kr) * D + c0 + co);
            }
            __syncthreads();
            #pragma unroll 2
            for (int k4 = 0; k4 < 8; ++k4) {
                const int k = k4 * 4;
                float wv0 = ws[(k + 0) * 32 + lane];
                float wv1 = ws[(k + 1) * 32 + lane];
                float wv2 = ws[(k + 2) * 32 + lane];
                float wv3 = ws[(k + 3) * 32 + lane];
                #pragma unroll
                for (int i = 0; i < 8; ++i) {
                    const float4 cv = *(const float4*)(cbs + (r0 + i) * CBP + k);
                    acc[i] = fmaf(cv.x, wv0, acc[i]);
                    acc[i] = fmaf(cv.y, wv1, acc[i]);
                    acc[i] = fmaf(cv.z, wv2, acc[i]);
                    acc[i] = fmaf(cv.w, wv3, acc[i]);
                }
            }
        }
        __syncthreads();
        float* es = (float*)st;
        #pragma unroll
        for (int i = 0; i < 8; ++i) es[(r0 + i) * CBP + lane] = acc[i];
        __syncthreads();
        if (tid < 128) {
            const int rl = tid >> 1, hh = tid & 1;
            const int grow = rg + rl;
            const int e = grow & 7;
            float4 v[4];
            #pragma unroll
            for (int i = 0; i < 4; ++i) v[i] = *(float4*)(es + rl * CBP + hh * 16 + i * 4);
            split16(v, &g_esplit[b >> 1][grow * 128], hh * 2, e);
        }
        return;
    }
    if (b == 32) {
        const int c = tid >> 1, h = tid & 1;
        const float* cp = CB + (size_t)c * D + h * 256;
        const float* bp = B + h * 256;
        float s2 = 0.f, sb = 0.f;
        #pragma unroll 4
        for (int k = 0; k < 64; ++k) {
            float4 v = ((const float4*)cp)[k];
            float4 bv = ((const float4*)bp)[k];
            s2 += v.x * v.x + v.y * v.y + v.z * v.z + v.w * v.w;
            sb += v.x * bv.x + v.y * bv.y + v.z * bv.z + v.w * bv.w;
        }
        s2 += __shfl_xor_sync(0xffffffffu, s2, 1);
        sb += __shfl_xor_sync(0xffffffffu, sb, 1);
        if (!h) g_tvec[c] = s2 - 2.f * sb;
        return;
    }

    const int r = tid >> 1, h = tid & 1, e = r & 7;
    const float* src0;
    char* dst;
    if (b < 97) {
        const int bb = b - 33;
        const int ct = bb >> 4, s = bb & 15;
        src0 = W + (size_t)(ct * 128 + r) * D + s * 32 + h * 16;
        dst = &g_wsplit[ct][s][0];
    } else {
        const int bb = b - 97;
        const int rb = bb >> 4, s = bb & 15;
        src0 = X + (size_t)(rb * 128 + r) * D + s * 32 + h * 16;
        dst = &g_xsplit[rb][s][0];
    }
    float4 v[4];
    #pragma unroll
    for (int i = 0; i < 4; ++i) v[i] = ((const float4*)src0)[i];
    split16(v, &st[r * 128], h * 2, e);
    __syncthreads();
    #pragma unroll
    for (int k = 0; k < 4; ++k)
        *(uint4*)(dst + tid * 16 + k * 4096) = *(const uint4*)(st + tid * 16 + k * 4096);
}

// ---------------------------------------------------------------- per-stage MMA (128x128x32, split-2)
// Three ILP passes: hh over all (mb,nb), then hl, then lh. Per-acc order is
// unchanged (hh -> hl -> lh) so results are bit-identical; between reuses of
// any accumulator there are now 16 independent HMMAs (RAW stalls hidden).
DEVINL void stage_mma(u32 aT, int tid, float acc[4][4][4]) {
    const int lane = tid & 31, w = tid >> 5;
    const int mw = w >> 2, nw = w & 3;
    const int eL = lane & 7;
    const int rA = lane & 15, cAk = lane >> 4;
    const int rB0 = nw * 32 + ((lane >> 4) << 3) + (lane & 7);
    const int cBk = (lane >> 3) & 1;
    const u32 bT = aT + TILE_B;

    #pragma unroll
    for (int kk = 0; kk < 2; ++kk) {
        u32 ahi[4][4], alo[4][4], bhi[4][2], blo[4][2];
        const int swA = (kk * 2 + cAk) ^ eL;
        #pragma unroll
        for (int mb = 0; mb < 4; ++mb) {
            const u32 base = aT + (mw * 64 + mb * 16 + rA) * 128;
            ldsm4(ahi[mb][0], ahi[mb][1], ahi[mb][2], ahi[mb][3], base + (swA << 4));
            ldsm4(alo[mb][0], alo[mb][1], alo[mb][2], alo[mb][3], base + ((swA ^ 4) << 4));
        }
        const int swB = (kk * 2 + cBk) ^ eL;
        #pragma unroll
        for (int bp = 0; bp < 2; ++bp) {
            const u32 base = bT + (rB0 + bp * 16) * 128;
            u32 r0, r1, r2, r3;
            ldsm4(r0, r1, r2, r3, base + (swB << 4));
            bhi[bp*2][0] = r0; bhi[bp*2][1] = r1;
            bhi[bp*2+1][0] = r2; bhi[bp*2+1][1] = r3;
            ldsm4(r0, r1, r2, r3, base + ((swB ^ 4) << 4));
            blo[bp*2][0] = r0; blo[bp*2][1] = r1;
            blo[bp*2+1][0] = r2; blo[bp*2+1][1] = r3;
        }
        #pragma unroll
        for (int mb = 0; mb < 4; ++mb)
            #pragma unroll
            for (int nb = 0; nb < 4; ++nb)
                mma_f16(acc[mb][nb], ahi[mb], bhi[nb]);
        #pragma unroll
        for (int mb = 0; mb < 4; ++mb)
            #pragma unroll
            for (int nb = 0; nb < 4; ++nb)
                mma_f16(acc[mb][nb], ahi[mb], blo[nb]);
        #pragma unroll
        for (int mb = 0; mb < 4; ++mb)
            #pragma unroll
            for (int nb = 0; nb < 4; ++nb)
                mma_f16(acc[mb][nb], alo[mb], bhi[nb]);
    }
}

// ---------------------------------------------------------------- fused GEMM + VQ
// grid (5, 256): ct<4 -> Z tile epilogue; ct==4 -> B=E, argmin + gather epilogue.
__global__ void __launch_bounds__(256, 2)
fused_hmma(const float* __restrict__ bias, const float* __restrict__ CB,
           float* __restrict__ Z, float* __restrict__ Q1, float* __restrict__ Q2)
{
    extern __shared__ char smc[];
    float* scn  = (float*)(smc + LOOP_SMEM);
    ull*   wb   = (ull*)  (smc + LOOP_SMEM + 512);
    int*   bidx = (int*)  (smc + LOOP_SMEM + 512 + 4096);

    const u32 sb = smem_u32(smc);
    const int tid = threadIdx.x;
    const int ct = blockIdx.x, rb = blockIdx.y;      // ct fast -> X L2 reuse
    const int li = tid & 127;

    if (ct == 4 && tid < NC) scn[tid] = g_tvec[tid];

    const char* srcBase = (tid < 128) ? &g_xsplit[rb][0][0]
                        : (ct < 4 ? &g_wsplit[ct][0][0] : &g_esplit[0][0]);
    const u32 dstBase = ((tid < 128) ? 0u : (u32)TILE_B) + li * 16;

    #define F_ISSUE(s, buf) do {                                              \
        const char* _src = srcBase + (s) * TILE_B + li * 16;                  \
        const u32 _d = sb + (buf) * STAGE_B + dstBase;                        \
        _Pragma("unroll")                                                     \
        for (int _k = 0; _k < 8; ++_k) cp16(_d + _k * 2048, _src + _k * 2048);\
    } while (0)

    F_ISSUE(0, 0); cp_commit();
    F_ISSUE(1, 1); cp_commit();

    float acc[4][4][4] = {};
    int buf = 0;
    #pragma unroll 1
    for (int s = 0; s < 16; ++s) {
        cp_wait1();
        __syncthreads();
        int b2 = buf + 2; if (b2 >= 3) b2 -= 3;
        if (s + 2 < 16) F_ISSUE(s + 2, b2);
        cp_commit();
        stage_mma(sb + buf * STAGE_B, tid, acc);
        if (++buf == 3) buf = 0;
    }
    #undef F_ISSUE

    cp_wait0();
    __syncthreads();

    const int lane = tid & 31, w = tid >> 5;
    const int mw = w >> 2, nw = w & 3;
    const int row0 = rb * 128;

    if (ct < 4) {
        // ---- Z epilogue: stage in smem, add bias, coalesced fp32 store
        float* zs = (float*)smc;                      // [128][132] = 67584 B
        const int col0 = ct * 128;
        #pragma unroll
        for (int nb = 0; nb < 4; ++nb) {
            const int cb = nw * 32 + nb * 8 + (lane & 3) * 2;
            const float2 bv = *(const float2*)&bias[col0 + cb];
            #pragma unroll
            for (int mb = 0; mb < 4; ++mb) {
                const int rr = mw * 64 + mb * 16 + (lane >> 2);
                *(float2*)&zs[rr * 132 + cb] =
                    make_float2(acc[mb][nb][0] + bv.x, acc[mb][nb][1] + bv.y);
                *(float2*)&zs[(rr + 8) * 132 + cb] =
                    make_float2(acc[mb][nb][2] + bv.x, acc[mb][nb][3] + bv.y);
            }
        }
        __syncthreads();
        #pragma unroll
        for (int it = 0; it < 16; ++it) {
            const int idx = tid + it * 256;           // 4096 float4 slots
            const int rr = idx >> 5, c4 = (idx & 31) * 4;
            float4 v = *(float4*)&zs[rr * 132 + c4];
            *(float4*)&Z[(size_t)(row0 + rr) * D + col0 + c4] = v;
        }
    } else {
        // ---- VQ epilogue: score = tvec[code] - 2*dot ; argmin ; gather
        #pragma unroll
        for (int mb = 0; mb < 4; ++mb) {
            #pragma unroll
            for (int rh = 0; rh < 2; ++rh) {
                ull best = ~0ull;
                #pragma unroll
                for (int nb = 0; nb < 4; ++nb) {
                    #pragma unroll
                    for (int j = 0; j < 2; ++j) {
                        const int code = nw * 32 + nb * 8 + (lane & 3) * 2 + j;
                        const float sc = fmaf(-2.f, acc[mb][nb][rh * 2 + j], scn[code]);
                        u32 o = __float_as_uint(sc);
                        o = (o & 0x80000000u) ? ~o : (o | 0x80000000u);
                        const ull key = ((ull)o << 32) | (u32)code;
                        if (key < best) best = key;
                    }
                }
                ull t = __shfl_xor_sync(0xffffffffu, best, 1); if (t < best) best = t;
                t     = __shfl_xor_sync(0xffffffffu, best, 2); if (t < best) best = t;
                const int rowl = mw * 64 + mb * 16 + rh * 8 + (lane >> 2);
                if ((lane & 3) == 0) wb[rowl * 4 + nw] = best;
            }
        }
        __syncthreads();

        if (tid < 128) {
            ull m = wb[tid * 4];
            ull a = wb[tid * 4 + 1]; if (a < m) m = a;
            a = wb[tid * 4 + 2];     if (a < m) m = a;
            a = wb[tid * 4 + 3];     if (a < m) m = a;
            bidx[tid] = (int)(m & 0xffffffffu);
        }
        __syncthreads();

        for (int rr = w; rr < 128; rr += 8) {
            const int idx = bidx[rr];
            const float4* s4 = (const float4*)(CB + (size_t)idx * D);
            float4* o1 = (float4*)(Q1 + (size_t)(row0 + rr) * D);
            float4* o2 = (float4*)(Q2 + (size_t)(row0 + rr) * D);
            #pragma unroll
            for (int i = lane; i < D / 4; i += 32) {
                const float4 vv = s4[i];
                o1[i] = vv;
                o2[i] = vv;
            }
        }
    }
}

// ---------------------------------------------------------------- launcher
extern "C" void kernel_launch(void* const* d_in, const int* in_sizes, int n_in,
                              void* d_out, int out_size)
{
    const float* x  = (const float*)d_in[0];
    const float* W  = (const float*)d_in[1];
    const float* b  = (const float*)d_in[2];
    const float* cb = (const float*)d_in[3];

    const int M = in_sizes[0] / D;            // 32768

    float* out = (float*)d_out;
    float* q1 = out;
    float* q2 = out + (size_t)M * D;
    float* z  = out + (size_t)2 * M * D;

    prepass_kernel<<<97 + (M / 128) * 16, 256>>>(x, W, b, cb);

    cudaFuncSetAttribute(fused_hmma, cudaFuncAttributeMaxDynamicSharedMemorySize, FUSED_SMEM);
    fused_hmma<<<dim3(5, M / 128), 256, FUSED_SMEM>>>(b, cb, z, q1, q2);
}

// round 16
// speedup vs baseline: 1.6216x; 1.0824x over previous
#include <cuda_runtime.h>
#include <cuda_fp16.h>
#include <cstdint>
#include <cstddef>

#define DEVINL __device__ __forceinline__
using u32 = uint32_t;
using ull = unsigned long long;

constexpr int D  = 512;
constexpr int NC = 128;

constexpr int TILE_B   = 16384;            // one 128-row x 128B packed tile (hi|lo)
constexpr int STAGE_B  = 2 * TILE_B;       // A tile + B tile
constexpr int NSTAGE   = 3;
constexpr int LOOP_SMEM = NSTAGE * STAGE_B;            // 98304
// extras: scn(512) wb(4096) bidx(512) mbars(64)
constexpr int FUSED_SMEM = LOOP_SMEM + 512 + 4096 + 512 + 64;

constexpr int CBP = 36;                    // padded CB row stride (floats)

__device__ float g_tvec[NC];               // ||c||^2 - 2 b.c
__device__ __align__(128) char g_xsplit[256][16][TILE_B];   // 64 MB
__device__ __align__(128) char g_wsplit[4][16][TILE_B];     // 1 MB
__device__ __align__(128) char g_esplit[16][TILE_B];        // 256 KB (E = CB@W, split)

// ---------------------------------------------------------------- helpers
DEVINL u32 smem_u32(const void* p) {
    u32 a;
    asm("{ .reg .u64 t; cvta.to.shared.u64 t, %1; cvt.u32.u64 %0, t; }"
        : "=r"(a) : "l"(p));
    return a;
}
DEVINL void ldsm4(u32& r0, u32& r1, u32& r2, u32& r3, u32 a) {
    asm volatile("ldmatrix.sync.aligned.m8n8.x4.shared.b16 {%0,%1,%2,%3}, [%4];"
                 : "=r"(r0), "=r"(r1), "=r"(r2), "=r"(r3) : "r"(a));
}
DEVINL void mma_f16(float c[4], const u32 a[4], const u32 b[2]) {
    asm volatile(
        "mma.sync.aligned.m16n8k16.row.col.f32.f16.f16.f32 "
        "{%0,%1,%2,%3},{%4,%5,%6,%7},{%8,%9},{%0,%1,%2,%3};"
        : "+f"(c[0]), "+f"(c[1]), "+f"(c[2]), "+f"(c[3])
        : "r"(a[0]), "r"(a[1]), "r"(a[2]), "r"(a[3]), "r"(b[0]), "r"(b[1]));
}
DEVINL u32 pack_h2(__half a, __half b) {
    __half2 h = __halves2half2(a, b);
    return *reinterpret_cast<u32*>(&h);
}
DEVINL void fsplit(float x, __half& h, __half& l) {
    h = __float2half_rn(x);
    l = __float2half_rn(x - __half2float(h));
}
// ---- mbarrier + bulk-copy primitives (sm_90 baseline features)
DEVINL void mbar_init(u32 a, u32 cnt) {
    asm volatile("mbarrier.init.shared.b64 [%0], %1;" :: "r"(a), "r"(cnt) : "memory");
}
DEVINL void mbar_expect_tx(u32 a, u32 tx) {
    asm volatile("mbarrier.arrive.expect_tx.shared.b64 _, [%0], %1;"
                 :: "r"(a), "r"(tx) : "memory");
}
DEVINL void mbar_arrive(u32 a) {
    asm volatile("mbarrier.arrive.shared.b64 _, [%0];" :: "r"(a) : "memory");
}
DEVINL void mbar_wait(u32 a, u32 parity) {
    asm volatile(
        "{\n\t.reg .pred P1;\n"
        "LW%=:\n\t"
        "mbarrier.try_wait.parity.shared.b64 P1, [%0], %1, 0x989680;\n\t"
        "@P1 bra.uni LD%=;\n\t"
        "bra.uni LW%=;\n"
        "LD%=:\n\t}"
        :: "r"(a), "r"(parity) : "memory");
}
DEVINL void cp_bulk(u32 dst, const void* src, u32 bytes, u32 mbar) {
    asm volatile(
        "cp.async.bulk.shared::cta.global.mbarrier::complete_tx::bytes "
        "[%0], [%1], %2, [%3];"
        :: "r"(dst), "l"(src), "r"(bytes), "r"(mbar) : "memory");
}

// split 16 fp32 into 2 hi + 2 lo 16B chunks of a packed tile row.
DEVINL void split16(const float4 v[4], char* drow, int c0, int e) {
    #pragma unroll
    for (int c2 = 0; c2 < 2; ++c2) {
        const float f[8] = { v[2*c2].x, v[2*c2].y, v[2*c2].z, v[2*c2].w,
                             v[2*c2+1].x, v[2*c2+1].y, v[2*c2+1].z, v[2*c2+1].w };
        __half hh[8], ll[8];
        #pragma unroll
        for (int j = 0; j < 8; ++j) fsplit(f[j], hh[j], ll[j]);
        uint4 uh = make_uint4(pack_h2(hh[0], hh[1]), pack_h2(hh[2], hh[3]),
                              pack_h2(hh[4], hh[5]), pack_h2(hh[6], hh[7]));
        uint4 ul = make_uint4(pack_h2(ll[0], ll[1]), pack_h2(ll[2], ll[3]),
                              pack_h2(ll[4], ll[5]), pack_h2(ll[6], ll[7]));
        const int c = c0 + c2;
        *(uint4*)(drow + (((c)     ^ e) << 4)) = uh;
        *(uint4*)(drow + (((c ^ 4) ^ e) << 4)) = ul;
    }
}

// ---------------------------------------------------------------- prepass (unchanged from R15)
__global__ void prepass_kernel(const float* __restrict__ X,
                               const float* __restrict__ W,
                               const float* __restrict__ B,
                               const float* __restrict__ CB) {
    __shared__ __align__(16) char st[TILE_B + 2048];
    __shared__ float ws[1024];
    const int b = blockIdx.x;
    const int tid = threadIdx.x;
    const int lane = tid & 31, w = tid >> 5;

    if (b < 32) {
        const int c0 = (b >> 1) * 32;
        const int rg = (b & 1) * 64;
        float* cbs = (float*)st;
        float acc[8];
        #pragma unroll
        for (int i = 0; i < 8; ++i) acc[i] = 0.f;
        const int r0 = w * 8;

        for (int kc = 0; kc < 16; ++kc) {
            const int k0 = kc * 32;
            __syncthreads();
            {
                const int rr = tid >> 2, q = tid & 3;
                const float4* src = (const float4*)(CB + (size_t)(rg + rr) * D + k0 + q * 8);
                float4* dstv = (float4*)(cbs + rr * CBP + q * 8);
                dstv[0] = src[0];
                dstv[1] = src[1];
            }
            {
                const int kr = tid >> 3, co = (tid & 7) * 4;
                *(float4*)(ws + kr * 32 + co) =
                    *(const float4*)(W + (size_t)(k0 + kr) * D + c0 + co);
            }
            __syncthreads();
            #pragma unroll 2
            for (int k4 = 0; k4 < 8; ++k4) {
                const int k = k4 * 4;
                float wv0 = ws[(k + 0) * 32 + lane];
                float wv1 = ws[(k + 1) * 32 + lane];
                float wv2 = ws[(k + 2) * 32 + lane];
                float wv3 = ws[(k + 3) * 32 + lane];
                #pragma unroll
                for (int i = 0; i < 8; ++i) {
                    const float4 cv = *(const float4*)(cbs + (r0 + i) * CBP + k);
                    acc[i] = fmaf(cv.x, wv0, acc[i]);
                    acc[i] = fmaf(cv.y, wv1, acc[i]);
                    acc[i] = fmaf(cv.z, wv2, acc[i]);
                    acc[i] = fmaf(cv.w, wv3, acc[i]);
                }
            }
        }
        __syncthreads();
        float* es = (float*)st;
        #pragma unroll
        for (int i = 0; i < 8; ++i) es[(r0 + i) * CBP + lane] = acc[i];
        __syncthreads();
        if (tid < 128) {
            const int rl = tid >> 1, hh = tid & 1;
            const int grow = rg + rl;
            const int e = grow & 7;
            float4 v[4];
            #pragma unroll
            for (int i = 0; i < 4; ++i) v[i] = *(float4*)(es + rl * CBP + hh * 16 + i * 4);
            split16(v, &g_esplit[b >> 1][grow * 128], hh * 2, e);
        }
        return;
    }
    if (b == 32) {
        const int c = tid >> 1, h = tid & 1;
        const float* cp = CB + (size_t)c * D + h * 256;
        const float* bp = B + h * 256;
        float s2 = 0.f, sb = 0.f;
        #pragma unroll 4
        for (int k = 0; k < 64; ++k) {
            float4 v = ((const float4*)cp)[k];
            float4 bv = ((const float4*)bp)[k];
            s2 += v.x * v.x + v.y * v.y + v.z * v.z + v.w * v.w;
            sb += v.x * bv.x + v.y * bv.y + v.z * bv.z + v.w * bv.w;
        }
        s2 += __shfl_xor_sync(0xffffffffu, s2, 1);
        sb += __shfl_xor_sync(0xffffffffu, sb, 1);
        if (!h) g_tvec[c] = s2 - 2.f * sb;
        return;
    }

    const int r = tid >> 1, h = tid & 1, e = r & 7;
    const float* src0;
    char* dst;
    if (b < 97) {
        const int bb = b - 33;
        const int ct = bb >> 4, s = bb & 15;
        src0 = W + (size_t)(ct * 128 + r) * D + s * 32 + h * 16;
        dst = &g_wsplit[ct][s][0];
    } else {
        const int bb = b - 97;
        const int rb = bb >> 4, s = bb & 15;
        src0 = X + (size_t)(rb * 128 + r) * D + s * 32 + h * 16;
        dst = &g_xsplit[rb][s][0];
    }
    float4 v[4];
    #pragma unroll
    for (int i = 0; i < 4; ++i) v[i] = ((const float4*)src0)[i];
    split16(v, &st[r * 128], h * 2, e);
    __syncthreads();
    #pragma unroll
    for (int k = 0; k < 4; ++k)
        *(uint4*)(dst + tid * 16 + k * 4096) = *(const uint4*)(st + tid * 16 + k * 4096);
}

// ---------------------------------------------------------------- per-stage MMA (128x128x32, split-2)
DEVINL void stage_mma(u32 aT, int tid, float acc[4][4][4]) {
    const int lane = tid & 31, w = tid >> 5;
    const int mw = w >> 2, nw = w & 3;
    const int eL = lane & 7;
    const int rA = lane & 15, cAk = lane >> 4;
    const int rB0 = nw * 32 + ((lane >> 4) << 3) + (lane & 7);
    const int cBk = (lane >> 3) & 1;
    const u32 bT = aT + TILE_B;

    #pragma unroll
    for (int kk = 0; kk < 2; ++kk) {
        u32 ahi[4][4], alo[4][4], bhi[4][2], blo[4][2];
        const int swA = (kk * 2 + cAk) ^ eL;
        #pragma unroll
        for (int mb = 0; mb < 4; ++mb) {
            const u32 base = aT + (mw * 64 + mb * 16 + rA) * 128;
            ldsm4(ahi[mb][0], ahi[mb][1], ahi[mb][2], ahi[mb][3], base + (swA << 4));
            ldsm4(alo[mb][0], alo[mb][1], alo[mb][2], alo[mb][3], base + ((swA ^ 4) << 4));
        }
        const int swB = (kk * 2 + cBk) ^ eL;
        #pragma unroll
        for (int bp = 0; bp < 2; ++bp) {
            const u32 base = bT + (rB0 + bp * 16) * 128;
            u32 r0, r1, r2, r3;
            ldsm4(r0, r1, r2, r3, base + (swB << 4));
            bhi[bp*2][0] = r0; bhi[bp*2][1] = r1;
            bhi[bp*2+1][0] = r2; bhi[bp*2+1][1] = r3;
            ldsm4(r0, r1, r2, r3, base + ((swB ^ 4) << 4));
            blo[bp*2][0] = r0; blo[bp*2][1] = r1;
            blo[bp*2+1][0] = r2; blo[bp*2+1][1] = r3;
        }
        #pragma unroll
        for (int mb = 0; mb < 4; ++mb)
            #pragma unroll
            for (int nb = 0; nb < 4; ++nb) {
                mma_f16(acc[mb][nb], ahi[mb], bhi[nb]);
                mma_f16(acc[mb][nb], ahi[mb], blo[nb]);
                mma_f16(acc[mb][nb], alo[mb], bhi[nb]);
            }
    }
}

// ---------------------------------------------------------------- fused GEMM + VQ (bulk + mbarrier pipeline)
// grid (5, 256): ct<4 -> Z tile epilogue; ct==4 -> B=E, argmin + gather epilogue.
__global__ void __launch_bounds__(256, 2)
fused_hmma(const float* __restrict__ bias, const float* __restrict__ CB,
           float* __restrict__ Z, float* __restrict__ Q1, float* __restrict__ Q2)
{
    extern __shared__ char smc[];
    float* scn  = (float*)(smc + LOOP_SMEM);
    ull*   wb   = (ull*)  (smc + LOOP_SMEM + 512);
    int*   bidx = (int*)  (smc + LOOP_SMEM + 512 + 4096);

    const u32 sb = smem_u32(smc);
    const u32 mb = sb + LOOP_SMEM + 512 + 4096 + 512;  // full[3] @ +0, free[3] @ +24
    const int tid = threadIdx.x;
    const int ct = blockIdx.x, rb = blockIdx.y;        // ct fast -> X L2 reuse

    if (ct == 4 && tid < NC) scn[tid] = g_tvec[tid];

    const char* srcA = &g_xsplit[rb][0][0];
    const char* srcB = (ct < 4) ? &g_wsplit[ct][0][0] : &g_esplit[0][0];

    if (tid == 0) {
        #pragma unroll
        for (int i = 0; i < 3; ++i) {
            mbar_init(mb + i * 8, 1);          // full: single expect_tx arrive
            mbar_init(mb + 24 + i * 8, 256);   // free: all threads arrive
        }
    }
    __syncthreads();
    mbar_arrive(mb + 24 + 2 * 8);              // pre-complete free[2] phase 0 (256 arrives)

    if (tid == 0) {                            // prime stages 0 and 1
        mbar_expect_tx(mb + 0, 2 * TILE_B);
        cp_bulk(sb,                      srcA,          TILE_B, mb + 0);
        cp_bulk(sb + TILE_B,             srcB,          TILE_B, mb + 0);
        mbar_expect_tx(mb + 8, 2 * TILE_B);
        cp_bulk(sb + STAGE_B,            srcA + TILE_B, TILE_B, mb + 8);
        cp_bulk(sb + STAGE_B + TILE_B,   srcB + TILE_B, TILE_B, mb + 8);
    }

    float acc[4][4][4] = {};
    #pragma unroll 1
    for (int s = 0; s < 16; ++s) {
        const int u = s / 3;
        const int b = s - u * 3;
        const u32 ph = (u32)(u & 1);
        if (tid == 0 && s + 2 < 16) {
            const int s2 = s + 2;
            const int b2 = s2 - (s2 / 3) * 3;
            mbar_wait(mb + 24 + b2 * 8, ph);               // buffer free (reads of s-1 done)
            mbar_expect_tx(mb + b2 * 8, 2 * TILE_B);
            cp_bulk(sb + b2 * STAGE_B,          srcA + s2 * TILE_B, TILE_B, mb + b2 * 8);
            cp_bulk(sb + b2 * STAGE_B + TILE_B, srcB + s2 * TILE_B, TILE_B, mb + b2 * 8);
        }
        mbar_wait(mb + b * 8, ph);                          // data ready
        stage_mma(sb + b * STAGE_B, tid, acc);
        mbar_arrive(mb + 24 + b * 8);                       // reads of buffer b done
    }
    __syncthreads();

    const int lane = tid & 31, w = tid >> 5;
    const int mw = w >> 2, nw = w & 3;
    const int row0 = rb * 128;

    if (ct < 4) {
        // ---- Z epilogue: stage in smem, add bias, coalesced fp32 store
        float* zs = (float*)smc;                      // [128][132] = 67584 B
        const int col0 = ct * 128;
        #pragma unroll
        for (int nb = 0; nb < 4; ++nb) {
            const int cb = nw * 32 + nb * 8 + (lane & 3) * 2;
            const float2 bv = *(const float2*)&bias[col0 + cb];
            #pragma unroll
            for (int mbq = 0; mbq < 4; ++mbq) {
                const int rr = mw * 64 + mbq * 16 + (lane >> 2);
                *(float2*)&zs[rr * 132 + cb] =
                    make_float2(acc[mbq][nb][0] + bv.x, acc[mbq][nb][1] + bv.y);
                *(float2*)&zs[(rr + 8) * 132 + cb] =
                    make_float2(acc[mbq][nb][2] + bv.x, acc[mbq][nb][3] + bv.y);
            }
        }
        __syncthreads();
        #pragma unroll
        for (int it = 0; it < 16; ++it) {
            const int idx = tid + it * 256;           // 4096 float4 slots
            const int rr = idx >> 5, c4 = (idx & 31) * 4;
            float4 v = *(float4*)&zs[rr * 132 + c4];
            *(float4*)&Z[(size_t)(row0 + rr) * D + col0 + c4] = v;
        }
    } else {
        // ---- VQ epilogue: score = tvec[code] - 2*dot ; argmin ; gather
        #pragma unroll
        for (int mbq = 0; mbq < 4; ++mbq) {
            #pragma unroll
            for (int rh = 0; rh < 2; ++rh) {
                ull best = ~0ull;
                #pragma unroll
                for (int nb = 0; nb < 4; ++nb) {
                    #pragma unroll
                    for (int j = 0; j < 2; ++j) {
                        const int code = nw * 32 + nb * 8 + (lane & 3) * 2 + j;
                        const float sc = fmaf(-2.f, acc[mbq][nb][rh * 2 + j], scn[code]);
                        u32 o = __float_as_uint(sc);
                        o = (o & 0x80000000u) ? ~o : (o | 0x80000000u);
                        const ull key = ((ull)o << 32) | (u32)code;
                        if (key < best) best = key;
                    }
                }
                ull t = __shfl_xor_sync(0xffffffffu, best, 1); if (t < best) best = t;
                t     = __shfl_xor_sync(0xffffffffu, best, 2); if (t < best) best = t;
                const int rowl = mw * 64 + mbq * 16 + rh * 8 + (lane >> 2);
                if ((lane & 3) == 0) wb[rowl * 4 + nw] = best;
            }
        }
        __syncthreads();

        if (tid < 128) {
            ull m = wb[tid * 4];
            ull a = wb[tid * 4 + 1]; if (a < m) m = a;
            a = wb[tid * 4 + 2];     if (a < m) m = a;
            a = wb[tid * 4 + 3];     if (a < m) m = a;
            bidx[tid] = (int)(m & 0xffffffffu);
        }
        __syncthreads();

        for (int rr = w; rr < 128; rr += 8) {
            const int idx = bidx[rr];
            const float4* s4 = (const float4*)(CB + (size_t)idx * D);
            float4* o1 = (float4*)(Q1 + (size_t)(row0 + rr) * D);
            float4* o2 = (float4*)(Q2 + (size_t)(row0 + rr) * D);
            #pragma unroll
            for (int i = lane; i < D / 4; i += 32) {
                const float4 vv = s4[i];
                o1[i] = vv;
                o2[i] = vv;
            }
        }
    }
}

// ---------------------------------------------------------------- launcher
extern "C" void kernel_launch(void* const* d_in, const int* in_sizes, int n_in,
                              void* d_out, int out_size)
{
    const float* x  = (const float*)d_in[0];
    const float* W  = (const float*)d_in[1];
    const float* b  = (const float*)d_in[2];
    const float* cb = (const float*)d_in[3];

    const int M = in_sizes[0] / D;            // 32768

    float* out = (float*)d_out;
    float* q1 = out;
    float* q2 = out + (size_t)M * D;
    float* z  = out + (size_t)2 * M * D;

    prepass_kernel<<<97 + (M / 128) * 16, 256>>>(x, W, b, cb);

    cudaFuncSetAttribute(fused_hmma, cudaFuncAttributeMaxDynamicSharedMemorySize, FUSED_SMEM);
    fused_hmma<<<dim3(5, M / 128), 256, FUSED_SMEM>>>(b, cb, z, q1, q2);
}

// round 17
// speedup vs baseline: 1.6770x; 1.0341x over previous
#include <cuda_runtime.h>
#include <cuda_fp16.h>
#include <cstdint>
#include <cstddef>

#define DEVINL __device__ __forceinline__
using u32 = uint32_t;
using ull = unsigned long long;

constexpr int D  = 512;
constexpr int NC = 128;

constexpr int TILE_B   = 16384;            // one 128-row x 128B packed tile (hi|lo)
constexpr int STAGE_B  = 2 * TILE_B;       // A tile + B tile
constexpr int NSTAGE   = 3;
constexpr int LOOP_SMEM = NSTAGE * STAGE_B;            // 98304
// extras: scn(512) wb(4096) bidx(512) mbars(64)
constexpr int FUSED_SMEM = LOOP_SMEM + 512 + 4096 + 512 + 64;

constexpr int CBP = 36;                    // padded smem row stride (floats), 144B

__device__ float g_tvec[NC];               // ||c||^2 - 2 b.c
__device__ __align__(128) char g_xsplit[256][16][TILE_B];   // 64 MB
__device__ __align__(128) char g_wsplit[4][16][TILE_B];     // 1 MB
__device__ __align__(128) char g_esplit[16][TILE_B];        // 256 KB (E = CB@W, split)

// ---------------------------------------------------------------- helpers
DEVINL u32 smem_u32(const void* p) {
    u32 a;
    asm("{ .reg .u64 t; cvta.to.shared.u64 t, %1; cvt.u32.u64 %0, t; }"
        : "=r"(a) : "l"(p));
    return a;
}
DEVINL void ldsm4(u32& r0, u32& r1, u32& r2, u32& r3, u32 a) {
    asm volatile("ldmatrix.sync.aligned.m8n8.x4.shared.b16 {%0,%1,%2,%3}, [%4];"
                 : "=r"(r0), "=r"(r1), "=r"(r2), "=r"(r3) : "r"(a));
}
DEVINL void mma_f16(float c[4], const u32 a[4], const u32 b[2]) {
    asm volatile(
        "mma.sync.aligned.m16n8k16.row.col.f32.f16.f16.f32 "
        "{%0,%1,%2,%3},{%4,%5,%6,%7},{%8,%9},{%0,%1,%2,%3};"
        : "+f"(c[0]), "+f"(c[1]), "+f"(c[2]), "+f"(c[3])
        : "r"(a[0]), "r"(a[1]), "r"(a[2]), "r"(a[3]), "r"(b[0]), "r"(b[1]));
}
DEVINL u32 pack_h2(__half a, __half b) {
    __half2 h = __halves2half2(a, b);
    return *reinterpret_cast<u32*>(&h);
}
DEVINL void fsplit(float x, __half& h, __half& l) {
    h = __float2half_rn(x);
    l = __float2half_rn(x - __half2float(h));
}
// ---- mbarrier + bulk-copy primitives (sm_90 baseline features)
DEVINL void mbar_init(u32 a, u32 cnt) {
    asm volatile("mbarrier.init.shared.b64 [%0], %1;" :: "r"(a), "r"(cnt) : "memory");
}
DEVINL void mbar_expect_tx(u32 a, u32 tx) {
    asm volatile("mbarrier.arrive.expect_tx.shared.b64 _, [%0], %1;"
                 :: "r"(a), "r"(tx) : "memory");
}
DEVINL void mbar_arrive(u32 a) {
    asm volatile("mbarrier.arrive.shared.b64 _, [%0];" :: "r"(a) : "memory");
}
DEVINL void mbar_wait(u32 a, u32 parity) {
    asm volatile(
        "{\n\t.reg .pred P1;\n"
        "LW%=:\n\t"
        "mbarrier.try_wait.parity.acquire.cta.shared::cta.b64 P1, [%0], %1, 0x989680;\n\t"
        "@P1 bra.uni LD%=;\n\t"
        "bra.uni LW%=;\n"
        "LD%=:\n\t}"
        :: "r"(a), "r"(parity) : "memory");
}
DEVINL void cp_bulk(u32 dst, const void* src, u32 bytes, u32 mbar) {
    asm volatile(
        "cp.async.bulk.shared::cta.global.mbarrier::complete_tx::bytes "
        "[%0], [%1], %2, [%3];"
        :: "r"(dst), "l"(src), "r"(bytes), "r"(mbar) : "memory");
}

// split 16 fp32 into 2 hi + 2 lo 16B chunks of a packed tile row.
DEVINL void split16(const float4 v[4], char* drow, int c0, int e) {
    #pragma unroll
    for (int c2 = 0; c2 < 2; ++c2) {
        const float f[8] = { v[2*c2].x, v[2*c2].y, v[2*c2].z, v[2*c2].w,
                             v[2*c2+1].x, v[2*c2+1].y, v[2*c2+1].z, v[2*c2+1].w };
        __half hh[8], ll[8];
        #pragma unroll
        for (int j = 0; j < 8; ++j) fsplit(f[j], hh[j], ll[j]);
        uint4 uh = make_uint4(pack_h2(hh[0], hh[1]), pack_h2(hh[2], hh[3]),
                              pack_h2(hh[4], hh[5]), pack_h2(hh[6], hh[7]));
        uint4 ul = make_uint4(pack_h2(ll[0], ll[1]), pack_h2(ll[2], ll[3]),
                              pack_h2(ll[4], ll[5]), pack_h2(ll[6], ll[7]));
        const int c = c0 + c2;
        *(uint4*)(drow + (((c)     ^ e) << 4)) = uh;
        *(uint4*)(drow + (((c ^ 4) ^ e) << 4)) = ul;
    }
}

// ---------------------------------------------------------------- prepass (single launch)
// b<128: E micro-block (16 rows x 32 cols). b==128: tvec.
// [129,193): W tiles. [193,193+4096): X tiles.
__global__ void prepass_kernel(const float* __restrict__ X,
                               const float* __restrict__ W,
                               const float* __restrict__ B,
                               const float* __restrict__ CB) {
    __shared__ __align__(16) char st[TILE_B + 2048];
    __shared__ float ws[1024];
    const int b = blockIdx.x;
    const int tid = threadIdx.x;

    if (b < 128) {
        // E rows rgrp*16..+15, output cols cgrp*32..+31. E = CB @ W.
        const int rgrp = b >> 4, cgrp = b & 15;
        const int c0 = cgrp * 32;
        float* cbs = (float*)st;                 // CB chunk [16 rows][CBP]
        const int r  = tid >> 4;                 // 0..15 row
        const int cq = tid & 15;                 // 0..15 -> cols 2cq, 2cq+1
        float accx = 0.f, accy = 0.f;

        for (int kc = 0; kc < 16; ++kc) {
            const int j0 = kc * 32;
            __syncthreads();
            {   // stage CB chunk: 16 rows x 32 j (512 floats, 2/thread)
                const int rr = tid >> 4, jj = (tid & 15) * 2;
                *(float2*)(cbs + rr * CBP + jj) =
                    *(const float2*)(CB + (size_t)(rgrp * 16 + rr) * D + j0 + jj);
            }
            {   // stage W chunk: 32 j-rows x 32 cols
                const int jr = tid >> 3, co = (tid & 7) * 4;
                *(float4*)(ws + jr * 32 + co) =
                    *(const float4*)(W + (size_t)(j0 + jr) * D + c0 + co);
            }
            __syncthreads();
            #pragma unroll 8
            for (int k = 0; k < 32; ++k) {
                const float cbv = cbs[r * CBP + k];
                const float2 wv = *(const float2*)(ws + k * 32 + 2 * cq);
                accx = fmaf(cbv, wv.x, accx);
                accy = fmaf(cbv, wv.y, accy);
            }
        }
        __syncthreads();
        float* es = (float*)st;                  // reuse: [16 rows][CBP]
        es[r * CBP + 2 * cq]     = accx;
        es[r * CBP + 2 * cq + 1] = accy;
        __syncthreads();
        if (tid < 32) {
            const int rl = tid >> 1, hh = tid & 1;
            const int grow = rgrp * 16 + rl;     // global code row
            const int e = grow & 7;
            float4 v[4];
            #pragma unroll
            for (int i = 0; i < 4; ++i) v[i] = *(float4*)(es + rl * CBP + hh * 16 + i * 4);
            split16(v, &g_esplit[cgrp][grow * 128], hh * 2, e);
        }
        return;
    }
    if (b == 128) {
        const int c = tid >> 1, h = tid & 1;
        const float* cp = CB + (size_t)c * D + h * 256;
        const float* bp = B + h * 256;
        float s2 = 0.f, sb = 0.f;
        #pragma unroll 4
        for (int k = 0; k < 64; ++k) {
            float4 v = ((const float4*)cp)[k];
            float4 bv = ((const float4*)bp)[k];
            s2 += v.x * v.x + v.y * v.y + v.z * v.z + v.w * v.w;
            sb += v.x * bv.x + v.y * bv.y + v.z * bv.z + v.w * bv.w;
        }
        s2 += __shfl_xor_sync(0xffffffffu, s2, 1);
        sb += __shfl_xor_sync(0xffffffffu, sb, 1);
        if (!h) g_tvec[c] = s2 - 2.f * sb;
        return;
    }

    // W / X tile split (R8 layout: 16KB of st, 1 slice per block)
    const int r = tid >> 1, h = tid & 1, e = r & 7;
    const float* src0;
    char* dst;
    if (b < 193) {
        const int bb = b - 129;
        const int ct = bb >> 4, s = bb & 15;
        src0 = W + (size_t)(ct * 128 + r) * D + s * 32 + h * 16;
        dst = &g_wsplit[ct][s][0];
    } else {
        const int bb = b - 193;
        const int rb = bb >> 4, s = bb & 15;
        src0 = X + (size_t)(rb * 128 + r) * D + s * 32 + h * 16;
        dst = &g_xsplit[rb][s][0];
    }
    float4 v[4];
    #pragma unroll
    for (int i = 0; i < 4; ++i) v[i] = ((const float4*)src0)[i];
    split16(v, &st[r * 128], h * 2, e);
    __syncthreads();
    #pragma unroll
    for (int k = 0; k < 4; ++k)
        *(uint4*)(dst + tid * 16 + k * 4096) = *(const uint4*)(st + tid * 16 + k * 4096);
}

// ---------------------------------------------------------------- per-stage MMA (128x128x32, split-2)
DEVINL void stage_mma(u32 aT, int tid, float acc[4][4][4]) {
    const int lane = tid & 31, w = tid >> 5;
    const int mw = w >> 2, nw = w & 3;
    const int eL = lane & 7;
    const int rA = lane & 15, cAk = lane >> 4;
    const int rB0 = nw * 32 + ((lane >> 4) << 3) + (lane & 7);
    const int cBk = (lane >> 3) & 1;
    const u32 bT = aT + TILE_B;

    #pragma unroll
    for (int kk = 0; kk < 2; ++kk) {
        u32 ahi[4][4], alo[4][4], bhi[4][2], blo[4][2];
        const int swA = (kk * 2 + cAk) ^ eL;
        #pragma unroll
        for (int mb = 0; mb < 4; ++mb) {
            const u32 base = aT + (mw * 64 + mb * 16 + rA) * 128;
            ldsm4(ahi[mb][0], ahi[mb][1], ahi[mb][2], ahi[mb][3], base + (swA << 4));
            ldsm4(alo[mb][0], alo[mb][1], alo[mb][2], alo[mb][3], base + ((swA ^ 4) << 4));
        }
        const int swB = (kk * 2 + cBk) ^ eL;
        #pragma unroll
        for (int bp = 0; bp < 2; ++bp) {
            const u32 base = bT + (rB0 + bp * 16) * 128;
            u32 r0, r1, r2, r3;
            ldsm4(r0, r1, r2, r3, base + (swB << 4));
            bhi[bp*2][0] = r0; bhi[bp*2][1] = r1;
            bhi[bp*2+1][0] = r2; bhi[bp*2+1][1] = r3;
            ldsm4(r0, r1, r2, r3, base + ((swB ^ 4) << 4));
            blo[bp*2][0] = r0; blo[bp*2][1] = r1;
            blo[bp*2+1][0] = r2; blo[bp*2+1][1] = r3;
        }
        #pragma unroll
        for (int mb = 0; mb < 4; ++mb)
            #pragma unroll
            for (int nb = 0; nb < 4; ++nb) {
                mma_f16(acc[mb][nb], ahi[mb], bhi[nb]);
                mma_f16(acc[mb][nb], ahi[mb], blo[nb]);
                mma_f16(acc[mb][nb], alo[mb], bhi[nb]);
            }
    }
}

// ---------------------------------------------------------------- fused GEMM + VQ (bulk + mbarrier pipeline)
// grid (5, 256): ct<4 -> Z tile epilogue; ct==4 -> B=E, argmin + gather epilogue.
__global__ void __launch_bounds__(256, 2)
fused_hmma(const float* __restrict__ bias, const float* __restrict__ CB,
           float* __restrict__ Z, float* __restrict__ Q1, float* __restrict__ Q2)
{
    extern __shared__ char smc[];
    float* scn  = (float*)(smc + LOOP_SMEM);
    ull*   wb   = (ull*)  (smc + LOOP_SMEM + 512);
    int*   bidx = (int*)  (smc + LOOP_SMEM + 512 + 4096);

    const u32 sb = smem_u32(smc);
    const u32 mb = sb + LOOP_SMEM + 512 + 4096 + 512;  // full[3] @ +0, free[3] @ +24
    const int tid = threadIdx.x;
    const int ct = blockIdx.x, rb = blockIdx.y;        // ct fast -> X L2 reuse

    if (ct == 4 && tid < NC) scn[tid] = g_tvec[tid];

    const char* srcA = &g_xsplit[rb][0][0];
    const char* srcB = (ct < 4) ? &g_wsplit[ct][0][0] : &g_esplit[0][0];

    if (tid == 0) {
        #pragma unroll
        for (int i = 0; i < 3; ++i) {
            mbar_init(mb + i * 8, 1);          // full: single expect_tx arrive
            mbar_init(mb + 24 + i * 8, 256);   // free: all threads arrive
        }
    }
    __syncthreads();
    mbar_arrive(mb + 24 + 2 * 8);              // pre-complete free[2] phase 0

    if (tid == 0) {                            // prime stages 0 and 1
        mbar_expect_tx(mb + 0, 2 * TILE_B);
        cp_bulk(sb,                      srcA,          TILE_B, mb + 0);
        cp_bulk(sb + TILE_B,             srcB,          TILE_B, mb + 0);
        mbar_expect_tx(mb + 8, 2 * TILE_B);
        cp_bulk(sb + STAGE_B,            srcA + TILE_B, TILE_B, mb + 8);
        cp_bulk(sb + STAGE_B + TILE_B,   srcB + TILE_B, TILE_B, mb + 8);
    }

    float acc[4][4][4] = {};
    #pragma unroll 1
    for (int s = 0; s < 16; ++s) {
        const int u = s / 3;
        const int b = s - u * 3;
        const u32 ph = (u32)(u & 1);
        if (tid == 0 && s + 2 < 16) {
            const int s2 = s + 2;
            const int b2 = s2 - (s2 / 3) * 3;
            mbar_wait(mb + 24 + b2 * 8, ph);               // buffer free
            mbar_expect_tx(mb + b2 * 8, 2 * TILE_B);
            cp_bulk(sb + b2 * STAGE_B,          srcA + s2 * TILE_B, TILE_B, mb + b2 * 8);
            cp_bulk(sb + b2 * STAGE_B + TILE_B, srcB + s2 * TILE_B, TILE_B, mb + b2 * 8);
        }
        mbar_wait(mb + b * 8, ph);                          // data ready
        stage_mma(sb + b * STAGE_B, tid, acc);
        mbar_arrive(mb + 24 + b * 8);                       // reads done
    }
    __syncthreads();

    const int lane = tid & 31, w = tid >> 5;
    const int mw = w >> 2, nw = w & 3;
    const int row0 = rb * 128;

    if (ct < 4) {
        // ---- Z epilogue: stage in smem, add bias, coalesced fp32 store
        float* zs = (float*)smc;                      // [128][132]
        const int col0 = ct * 128;
        #pragma unroll
        for (int nb = 0; nb < 4; ++nb) {
            const int cb = nw * 32 + nb * 8 + (lane & 3) * 2;
            const float2 bv = *(const float2*)&bias[col0 + cb];
            #pragma unroll
            for (int mbq = 0; mbq < 4; ++mbq) {
                const int rr = mw * 64 + mbq * 16 + (lane >> 2);
                *(float2*)&zs[rr * 132 + cb] =
                    make_float2(acc[mbq][nb][0] + bv.x, acc[mbq][nb][1] + bv.y);
                *(float2*)&zs[(rr + 8) * 132 + cb] =
                    make_float2(acc[mbq][nb][2] + bv.x, acc[mbq][nb][3] + bv.y);
            }
        }
        __syncthreads();
        #pragma unroll
        for (int it = 0; it < 16; ++it) {
            const int idx = tid + it * 256;
            const int rr = idx >> 5, c4 = (idx & 31) * 4;
            float4 v = *(float4*)&zs[rr * 132 + c4];
            *(float4*)&Z[(size_t)(row0 + rr) * D + col0 + c4] = v;
        }
    } else {
        // ---- VQ epilogue: score = tvec[code] - 2*dot ; argmin ; gather
        #pragma unroll
        for (int mbq = 0; mbq < 4; ++mbq) {
            #pragma unroll
            for (int rh = 0; rh < 2; ++rh) {
                ull best = ~0ull;
                #pragma unroll
                for (int nb = 0; nb < 4; ++nb) {
                    #pragma unroll
                    for (int j = 0; j < 2; ++j) {
                        const int code = nw * 32 + nb * 8 + (lane & 3) * 2 + j;
                        const float sc = fmaf(-2.f, acc[mbq][nb][rh * 2 + j], scn[code]);
                        u32 o = __float_as_uint(sc);
                        o = (o & 0x80000000u) ? ~o : (o | 0x80000000u);
                        const ull key = ((ull)o << 32) | (u32)code;
                        if (key < best) best = key;
                    }
                }
                ull t = __shfl_xor_sync(0xffffffffu, best, 1); if (t < best) best = t;
                t     = __shfl_xor_sync(0xffffffffu, best, 2); if (t < best) best = t;
                const int rowl = mw * 64 + mbq * 16 + rh * 8 + (lane >> 2);
                if ((lane & 3) == 0) wb[rowl * 4 + nw] = best;
            }
        }
        __syncthreads();

        if (tid < 128) {
            ull m = wb[tid * 4];
            ull a = wb[tid * 4 + 1]; if (a < m) m = a;
            a = wb[tid * 4 + 2];     if (a < m) m = a;
            a = wb[tid * 4 + 3];     if (a < m) m = a;
            bidx[tid] = (int)(m & 0xffffffffu);
        }
        __syncthreads();

        for (int rr = w; rr < 128; rr += 8) {
            const int idx = bidx[rr];
            const float4* s4 = (const float4*)(CB + (size_t)idx * D);
            float4* o1 = (float4*)(Q1 + (size_t)(row0 + rr) * D);
            float4* o2 = (float4*)(Q2 + (size_t)(row0 + rr) * D);
            #pragma unroll
            for (int i = lane; i < D / 4; i += 32) {
                const float4 vv = s4[i];
                o1[i] = vv;
                o2[i] = vv;
            }
        }
    }
}

// ---------------------------------------------------------------- launcher
extern "C" void kernel_launch(void* const* d_in, const int* in_sizes, int n_in,
                              void* d_out, int out_size)
{
    const float* x  = (const float*)d_in[0];
    const float* W  = (const float*)d_in[1];
    const float* b  = (const float*)d_in[2];
    const float* cb = (const float*)d_in[3];

    const int M = in_sizes[0] / D;            // 32768

    float* out = (float*)d_out;
    float* q1 = out;
    float* q2 = out + (size_t)M * D;
    float* z  = out + (size_t)2 * M * D;

    prepass_kernel<<<193 + (M / 128) * 16, 256>>>(x, W, b, cb);

    cudaFuncSetAttribute(fused_hmma, cudaFuncAttributeMaxDynamicSharedMemorySize, FUSED_SMEM);
    fused_hmma<<<dim3(5, M / 128), 256, FUSED_SMEM>>>(b, cb, z, q1, q2);
}